// round 3
// baseline (speedup 1.0000x reference)
#include <cuda_runtime.h>
#include <math.h>

#define HID   128
#define MAXN  50000
#define MAXE  800000
#define RNUM  8
#define HEADS 4
#define FFDIM 512

// ---------------- scratch (device globals: allocation-free rule) ----------------
__device__ float    g_h1  [(size_t)MAXN*HID];
__device__ float    g_xr  [(size_t)RNUM*MAXN*HID];
__device__ float    g_ad  [(size_t)MAXN*128];       // per-node attn dots (padded GEMM out)
__device__ float    g_wattp[128*128];               // padded w_att (cols 64.. zero)
__device__ float    g_alpha[(size_t)MAXE*HEADS];    // logits
__device__ unsigned g_amax[(size_t)MAXN*HEADS];
__device__ float    g_den [(size_t)MAXN*HEADS];
__device__ float    g_msg [(size_t)MAXN*HID];       // unnormalized message sum
__device__ float    g_outc[(size_t)MAXN*HID];       // root GEMM + bias
__device__ float    g_h2  [(size_t)MAXN*HID];
__device__ float    g_t   [(size_t)MAXN*FFDIM];
__device__ float    g_er  [RNUM*HEADS];
__device__ int      g_cnt [RNUM];
__device__ int      g_pos [RNUM];
__device__ int      g_eord[MAXE];

// ---------------- helpers ----------------
__device__ __forceinline__ unsigned fenc(float f) {
    unsigned u = __float_as_uint(f);
    return (u & 0x80000000u) ? ~u : (u | 0x80000000u);
}
__device__ __forceinline__ float fdec(unsigned u) {
    return (u & 0x80000000u) ? __uint_as_float(u & 0x7fffffffu)
                             : __uint_as_float(~u);
}
__device__ __forceinline__ float geluf(float v) {
    return 0.5f * v * (1.0f + erff(v * 0.7071067811865475f));
}
__device__ __forceinline__ float eluf(float v) {
    return v > 0.0f ? v : expm1f(v);
}
__device__ __forceinline__ float lreluf(float v) {
    return v > 0.0f ? v : 0.2f * v;
}
__device__ __forceinline__ float tf32r(float v) {
    float o;
    asm("cvt.rna.tf32.f32 %0, %1;" : "=f"(o) : "f"(v));
    return o;
}

// ---------------- init: zero msg, amax, den, cnt ----------------
__global__ void init_kernel(int Nn) {
    int i = blockIdx.x * blockDim.x + threadIdx.x;
    if (i < Nn * (HID / 4)) ((float4*)g_msg)[i] = make_float4(0.f,0.f,0.f,0.f);
    if (i < Nn * HEADS) { g_amax[i] = 0u; g_den[i] = 0.0f; }
    if (i < RNUM) g_cnt[i] = 0;
}

__global__ void er_kernel(const float* __restrict__ emb,
                          const float* __restrict__ att_edge) {
    int t = threadIdx.x;
    int r = t >> 2, h = t & 3;
    float s = 0.0f;
    #pragma unroll
    for (int d = 0; d < 32; d++)
        s += emb[r * HID + h * 32 + d] * att_edge[h * 32 + d];
    g_er[r * HEADS + h] = s;
}

// w_att[i][c]:  c<32: src dots col (r*4+h);  32..63: dst;  64..127: zero
__global__ void watt_kernel(const float* __restrict__ weight,
                            const float* __restrict__ att_src,
                            const float* __restrict__ att_dst) {
    int idx = blockIdx.x * blockDim.x + threadIdx.x;   // 16384 entries
    if (idx >= 128 * 128) return;
    int i = idx >> 7, c = idx & 127;
    float s = 0.0f;
    if (c < 64) {
        const float* vec = (c < 32) ? att_src : att_dst;
        int cc = c & 31;
        int r = cc >> 2, h = cc & 3;
        const float* wrow = weight + (long)r * HID * HID + (long)i * HID + h * 32;
        #pragma unroll
        for (int d = 0; d < 32; d++) s += wrow[d] * vec[h * 32 + d];
    }
    g_wattp[i * 128 + c] = s;
}

// ---------------- layernorm (warp per row, 128 cols) ----------------
__global__ void ln_kernel(const float* __restrict__ x,
                          const float* __restrict__ w,
                          const float* __restrict__ b,
                          float* __restrict__ out, int Nn) {
    int gw = (blockIdx.x * blockDim.x + threadIdx.x) >> 5;
    int lane = threadIdx.x & 31;
    if (gw >= Nn) return;
    const float4 v = *(const float4*)(x + (size_t)gw * HID + lane * 4);
    float s = v.x + v.y + v.z + v.w;
    float q = v.x * v.x + v.y * v.y + v.z * v.z + v.w * v.w;
    #pragma unroll
    for (int o = 16; o; o >>= 1) {
        s += __shfl_xor_sync(0xffffffffu, s, o);
        q += __shfl_xor_sync(0xffffffffu, q, o);
    }
    float mu = s * (1.0f / HID);
    float var = q * (1.0f / HID) - mu * mu;
    float rstd = rsqrtf(var + 1e-5f);
    float4 wv = *(const float4*)(w + lane * 4);
    float4 bv = *(const float4*)(b + lane * 4);
    float4 o4;
    o4.x = (v.x - mu) * rstd * wv.x + bv.x;
    o4.y = (v.y - mu) * rstd * wv.y + bv.y;
    o4.z = (v.z - mu) * rstd * wv.z + bv.z;
    o4.w = (v.w - mu) * rstd * wv.w + bv.w;
    *(float4*)(out + (size_t)gw * HID + lane * 4) = o4;
}

// ---------------- tf32 tensor-core GEMM ----------------
#define APAD 20
#define BPAD 136
__global__ __launch_bounds__(256)
void gemm_tf32(const float* __restrict__ A, const float* __restrict__ B,
               float* __restrict__ C, const float* __restrict__ bias,
               const float* __restrict__ resid,
               int M, int K, int ncols, int act,
               long strideB, long strideC) {
    __shared__ float As[2][128][APAD];
    __shared__ float Bs[2][16][BPAD];

    const float* Bb = B + (long)blockIdx.z * strideB;
    float* Cb = C + (long)blockIdx.z * strideC;
    const int m0 = blockIdx.x * 128;
    const int n0 = blockIdx.y * 128;
    const int tid = threadIdx.x;
    const int wid = tid >> 5, lane = tid & 31;
    const int wm = wid >> 2, wn = wid & 3;
    const int g = lane >> 2, tg = lane & 3;

    float acc[4][4][4];
    #pragma unroll
    for (int i = 0; i < 4; i++)
        #pragma unroll
        for (int j = 0; j < 4; j++)
            #pragma unroll
            for (int c = 0; c < 4; c++) acc[i][j][c] = 0.0f;

    const int la_row0 = tid >> 2, la_q = tid & 3;
    const int lb_c = tid & 31;
    const int nk = K >> 4;

    {
        #pragma unroll
        for (int l = 0; l < 2; l++) {
            int row = la_row0 + l * 64;
            float4 v = make_float4(0.f,0.f,0.f,0.f);
            if (m0 + row < M)
                v = *(const float4*)(A + (long)(m0 + row) * K + la_q * 4);
            As[0][row][la_q*4+0] = tf32r(v.x);
            As[0][row][la_q*4+1] = tf32r(v.y);
            As[0][row][la_q*4+2] = tf32r(v.z);
            As[0][row][la_q*4+3] = tf32r(v.w);
        }
        #pragma unroll
        for (int l = 0; l < 2; l++) {
            int row = (tid >> 5) + l * 8;
            float4 v = *(const float4*)(Bb + (long)row * ncols + n0 + lb_c * 4);
            Bs[0][row][lb_c*4+0] = tf32r(v.x);
            Bs[0][row][lb_c*4+1] = tf32r(v.y);
            Bs[0][row][lb_c*4+2] = tf32r(v.z);
            Bs[0][row][lb_c*4+3] = tf32r(v.w);
        }
    }
    __syncthreads();

    for (int it = 0; it < nk; it++) {
        int buf = it & 1;
        float4 ra[2], rb[2];
        bool have_next = (it + 1 < nk);
        if (have_next) {
            int k0 = (it + 1) << 4;
            #pragma unroll
            for (int l = 0; l < 2; l++) {
                int row = la_row0 + l * 64;
                ra[l] = make_float4(0.f,0.f,0.f,0.f);
                if (m0 + row < M)
                    ra[l] = *(const float4*)(A + (long)(m0 + row) * K + k0 + la_q * 4);
            }
            #pragma unroll
            for (int l = 0; l < 2; l++) {
                int row = (tid >> 5) + l * 8;
                rb[l] = *(const float4*)(Bb + (long)(k0 + row) * ncols + n0 + lb_c * 4);
            }
        }

        #pragma unroll
        for (int kk = 0; kk < 16; kk += 8) {
            unsigned af[4][4];
            #pragma unroll
            for (int tm = 0; tm < 4; tm++) {
                int rb_ = wm * 64 + tm * 16;
                af[tm][0] = __float_as_uint(As[buf][rb_ + g     ][kk + tg    ]);
                af[tm][1] = __float_as_uint(As[buf][rb_ + g + 8 ][kk + tg    ]);
                af[tm][2] = __float_as_uint(As[buf][rb_ + g     ][kk + tg + 4]);
                af[tm][3] = __float_as_uint(As[buf][rb_ + g + 8 ][kk + tg + 4]);
            }
            unsigned bf0[4], bf1[4];
            #pragma unroll
            for (int tn = 0; tn < 4; tn++) {
                int cb = wn * 32 + tn * 8;
                bf0[tn] = __float_as_uint(Bs[buf][kk + tg    ][cb + g]);
                bf1[tn] = __float_as_uint(Bs[buf][kk + tg + 4][cb + g]);
            }
            #pragma unroll
            for (int tm = 0; tm < 4; tm++)
                #pragma unroll
                for (int tn = 0; tn < 4; tn++) {
                    asm volatile(
                        "mma.sync.aligned.m16n8k8.row.col.f32.tf32.tf32.f32 "
                        "{%0,%1,%2,%3}, {%4,%5,%6,%7}, {%8,%9}, {%0,%1,%2,%3};"
                        : "+f"(acc[tm][tn][0]), "+f"(acc[tm][tn][1]),
                          "+f"(acc[tm][tn][2]), "+f"(acc[tm][tn][3])
                        : "r"(af[tm][0]), "r"(af[tm][1]), "r"(af[tm][2]), "r"(af[tm][3]),
                          "r"(bf0[tn]), "r"(bf1[tn]));
                }
        }

        if (have_next) {
            int nb = 1 - buf;
            #pragma unroll
            for (int l = 0; l < 2; l++) {
                int row = la_row0 + l * 64;
                As[nb][row][la_q*4+0] = tf32r(ra[l].x);
                As[nb][row][la_q*4+1] = tf32r(ra[l].y);
                As[nb][row][la_q*4+2] = tf32r(ra[l].z);
                As[nb][row][la_q*4+3] = tf32r(ra[l].w);
            }
            #pragma unroll
            for (int l = 0; l < 2; l++) {
                int row = (tid >> 5) + l * 8;
                Bs[nb][row][lb_c*4+0] = tf32r(rb[l].x);
                Bs[nb][row][lb_c*4+1] = tf32r(rb[l].y);
                Bs[nb][row][lb_c*4+2] = tf32r(rb[l].z);
                Bs[nb][row][lb_c*4+3] = tf32r(rb[l].w);
            }
        }
        __syncthreads();
    }

    #pragma unroll
    for (int tm = 0; tm < 4; tm++) {
        int r0 = m0 + wm * 64 + tm * 16 + g;
        #pragma unroll
        for (int tn = 0; tn < 4; tn++) {
            int col = n0 + wn * 32 + tn * 8 + 2 * tg;
            float2 bv = make_float2(0.f, 0.f);
            if (bias) bv = *(const float2*)(bias + col);
            #pragma unroll
            for (int half = 0; half < 2; half++) {
                int row = r0 + half * 8;
                if (row >= M) continue;
                float v0 = acc[tm][tn][half*2+0] + bv.x;
                float v1 = acc[tm][tn][half*2+1] + bv.y;
                if (act == 1) { v0 = geluf(v0); v1 = geluf(v1); }
                if (resid) {
                    float2 rr = *(const float2*)(resid + (long)row * ncols + col);
                    v0 += rr.x; v1 += rr.y;
                }
                *(float2*)(Cb + (long)row * ncols + col) = make_float2(v0, v1);
            }
        }
    }
}

// ---------------- edge binning by relation ----------------
__global__ void bin_count(const int* __restrict__ et, int E) {
    __shared__ int c[RNUM];
    if (threadIdx.x < RNUM) c[threadIdx.x] = 0;
    __syncthreads();
    int e = blockIdx.x * blockDim.x + threadIdx.x;
    if (e < E) atomicAdd(&c[et[e]], 1);
    __syncthreads();
    if (threadIdx.x < RNUM && c[threadIdx.x])
        atomicAdd(&g_cnt[threadIdx.x], c[threadIdx.x]);
}
__global__ void bin_scan() {
    int o = 0;
    #pragma unroll
    for (int r = 0; r < RNUM; r++) { g_pos[r] = o; o += g_cnt[r]; }
}
__global__ void bin_scatter(const int* __restrict__ et, int E) {
    int e = blockIdx.x * blockDim.x + threadIdx.x;
    if (e >= E) return;
    int p = atomicAdd(&g_pos[et[e]], 1);
    g_eord[p] = e;
}

// ---------------- edge pass 1: logits + segment max ----------------
__global__ void edge_pass1(const int* __restrict__ ei, const int* __restrict__ et,
                           int E) {
    int e = blockIdx.x * blockDim.x + threadIdx.x;
    if (e >= E) return;
    int r = et[e];
    int s = ei[e];
    int d = ei[E + e];
    float4 as = *(const float4*)(g_ad + (long)s * 128 + r * 4);
    float4 ad = *(const float4*)(g_ad + (long)d * 128 + 32 + r * 4);
    float4 er = *(const float4*)(g_er + r * HEADS);
    float a0 = lreluf(as.x + ad.x + er.x);
    float a1 = lreluf(as.y + ad.y + er.y);
    float a2 = lreluf(as.z + ad.z + er.z);
    float a3 = lreluf(as.w + ad.w + er.w);
    *(float4*)(g_alpha + (long)e * HEADS) = make_float4(a0, a1, a2, a3);
    unsigned* am = g_amax + (long)d * HEADS;
    atomicMax(am + 0, fenc(a0));
    atomicMax(am + 1, fenc(a1));
    atomicMax(am + 2, fenc(a2));
    atomicMax(am + 3, fenc(a3));
}

// ---------------- edge pass 3: exp + den + message scatter (warp per edge) ------
// consumes r-sorted edge order g_eord for L2-resident xr gathers
__global__ void edge_pass3(const int* __restrict__ ei, const int* __restrict__ et,
                           int E, int Nn) {
    long gw = ((long)blockIdx.x * blockDim.x + threadIdx.x) >> 5;
    int lane = threadIdx.x & 31;
    if (gw >= E) return;
    int e = g_eord[gw];
    int r = et[e];
    int s = ei[e];
    int d = ei[E + e];
    int h = lane >> 3;
    float a  = g_alpha[(long)e * HEADS + h];
    float mx = fdec(g_amax[(long)d * HEADS + h]);
    float ex = expf(a - mx);
    if ((lane & 7) == 0) atomicAdd(g_den + (long)d * HEADS + h, ex);
    float4 xs = *(const float4*)(g_xr + ((long)r * Nn + s) * HID + lane * 4);
    float* o = g_msg + (long)d * HID + lane * 4;
    asm volatile("red.global.add.v4.f32 [%0], {%1,%2,%3,%4};"
                 :: "l"(o), "f"(xs.x * ex), "f"(xs.y * ex),
                    "f"(xs.z * ex), "f"(xs.w * ex)
                 : "memory");
}

// ---------------- post: normalize + root + elu + residual + LN2 ----------------
__global__ void post_kernel(const float* __restrict__ x,
                            const float* __restrict__ w,
                            const float* __restrict__ b,
                            float* __restrict__ x1out, int Nn) {
    int gw = (blockIdx.x * blockDim.x + threadIdx.x) >> 5;
    int lane = threadIdx.x & 31;
    if (gw >= Nn) return;
    int h = lane >> 3;
    float den = g_den[(long)gw * HEADS + h];
    float inv = 1.0f / (den + 1e-16f);
    float4 mg = *(const float4*)(g_msg + (size_t)gw * HID + lane * 4);
    float4 rt = *(const float4*)(g_outc + (size_t)gw * HID + lane * 4);
    float4 oc;
    oc.x = eluf(mg.x * inv + rt.x);
    oc.y = eluf(mg.y * inv + rt.y);
    oc.z = eluf(mg.z * inv + rt.z);
    oc.w = eluf(mg.w * inv + rt.w);
    float4 xv = *(const float4*)(x + (size_t)gw * HID + lane * 4);
    float4 x1 = make_float4(xv.x + oc.x, xv.y + oc.y, xv.z + oc.z, xv.w + oc.w);
    *(float4*)(x1out + (size_t)gw * HID + lane * 4) = x1;
    float s = x1.x + x1.y + x1.z + x1.w;
    float q = x1.x * x1.x + x1.y * x1.y + x1.z * x1.z + x1.w * x1.w;
    #pragma unroll
    for (int o = 16; o; o >>= 1) {
        s += __shfl_xor_sync(0xffffffffu, s, o);
        q += __shfl_xor_sync(0xffffffffu, q, o);
    }
    float mu = s * (1.0f / HID);
    float var = q * (1.0f / HID) - mu * mu;
    float rstd = rsqrtf(var + 1e-5f);
    float4 wv = *(const float4*)(w + lane * 4);
    float4 bv = *(const float4*)(b + lane * 4);
    float4 o4;
    o4.x = (x1.x - mu) * rstd * wv.x + bv.x;
    o4.y = (x1.y - mu) * rstd * wv.y + bv.y;
    o4.z = (x1.z - mu) * rstd * wv.z + bv.z;
    o4.w = (x1.w - mu) * rstd * wv.w + bv.w;
    *(float4*)(g_h2 + (size_t)gw * HID + lane * 4) = o4;
}

// ---------------- launch ----------------
extern "C" void kernel_launch(void* const* d_in, const int* in_sizes, int n_in,
                              void* d_out, int out_size) {
    const float* x          = (const float*)d_in[0];
    const float* weight     = (const float*)d_in[1];
    const float* root_w     = (const float*)d_in[2];
    const float* edge_emb   = (const float*)d_in[3];
    const float* att_src    = (const float*)d_in[4];
    const float* att_dst    = (const float*)d_in[5];
    const float* att_edge   = (const float*)d_in[6];
    const float* bias       = (const float*)d_in[7];
    const float* n1w        = (const float*)d_in[8];
    const float* n1b        = (const float*)d_in[9];
    const float* n2w        = (const float*)d_in[10];
    const float* n2b        = (const float*)d_in[11];
    const float* ffn_w1     = (const float*)d_in[12];
    const float* ffn_b1     = (const float*)d_in[13];
    const float* ffn_w2     = (const float*)d_in[14];
    const float* ffn_b2     = (const float*)d_in[15];
    const int*   edge_index = (const int*)d_in[16];
    const int*   edge_type  = (const int*)d_in[17];
    float* out = (float*)d_out;

    int N = in_sizes[0] / HID;
    int E = in_sizes[17];
    int R = in_sizes[1] / (HID * HID);

    float *p_h1, *p_xr, *p_ad, *p_wattp, *p_outc, *p_h2, *p_t;
    cudaGetSymbolAddress((void**)&p_h1,    g_h1);
    cudaGetSymbolAddress((void**)&p_xr,    g_xr);
    cudaGetSymbolAddress((void**)&p_ad,    g_ad);
    cudaGetSymbolAddress((void**)&p_wattp, g_wattp);
    cudaGetSymbolAddress((void**)&p_outc,  g_outc);
    cudaGetSymbolAddress((void**)&p_h2,    g_h2);
    cudaGetSymbolAddress((void**)&p_t,     g_t);

    int rowBlocks = (N + 7) / 8;
    int mTiles    = (N + 127) / 128;

    init_kernel<<<(N * HID / 4 + 255) / 256, 256>>>(N);
    er_kernel<<<1, 32>>>(edge_emb, att_edge);
    watt_kernel<<<64, 256>>>(weight, att_src, att_dst);
    ln_kernel<<<rowBlocks, 256>>>(x, n1w, n1b, p_h1, N);

    // edge binning by relation (independent of GEMMs)
    bin_count<<<(E + 255) / 256, 256>>>(edge_type, E);
    bin_scan<<<1, 1>>>();
    bin_scatter<<<(E + 255) / 256, 256>>>(edge_type, E);

    // attention dots via small GEMM: g_ad = h1 @ w_att (padded to 128 cols)
    gemm_tf32<<<dim3(mTiles, 1, 1), 256>>>(p_h1, p_wattp, p_ad, nullptr, nullptr,
                                           N, HID, 128, 0, 0, 0);
    // relation-wise projection: x_r[r] = h1 @ weight[r]
    gemm_tf32<<<dim3(mTiles, 1, R), 256>>>(p_h1, weight, p_xr, nullptr, nullptr,
                                           N, HID, HID, 0,
                                           (long)HID * HID, (long)N * HID);
    edge_pass1<<<(E + 255) / 256, 256>>>(edge_index, edge_type, E);

    // root term (separate buffer; messages go to g_msg)
    gemm_tf32<<<dim3(mTiles, 1, 1), 256>>>(p_h1, root_w, p_outc, bias, nullptr,
                                           N, HID, HID, 0, 0, 0);
    // fused exp + den + scatter, r-sorted for L2 locality
    edge_pass3<<<(E + 7) / 8, 256>>>(edge_index, edge_type, E, N);

    post_kernel<<<rowBlocks, 256>>>(x, n2w, n2b, out, N);

    gemm_tf32<<<dim3(mTiles, 4, 1), 256>>>(p_h2, ffn_w1, p_t, ffn_b1, nullptr,
                                           N, HID, FFDIM, 1, 0, 0);
    gemm_tf32<<<dim3(mTiles, 1, 1), 256>>>(p_t, ffn_w2, out, ffn_b2, out,
                                           N, FFDIM, HID, 0, 0, 0);
}

// round 4
// speedup vs baseline: 1.2788x; 1.2788x over previous
#include <cuda_runtime.h>
#include <math.h>

#define HID   128
#define MAXN  50000
#define MAXE  800000
#define RNUM  8
#define HEADS 4
#define FFDIM 512

// ---------------- scratch (device globals: allocation-free rule) ----------------
__device__ float    g_h1  [(size_t)MAXN*HID];
__device__ float    g_xr  [(size_t)RNUM*MAXN*HID];
__device__ float    g_ad  [(size_t)MAXN*128];       // per-node attn dots (padded GEMM out)
__device__ float    g_wattp[128*128];               // padded w_att (cols 64.. zero)
__device__ float    g_den [(size_t)MAXN*HEADS];
__device__ float    g_msg [(size_t)MAXN*HID];       // unnormalized message sum
__device__ float    g_outc[(size_t)MAXN*HID];       // root GEMM + bias
__device__ float    g_h2  [(size_t)MAXN*HID];
__device__ float    g_t   [(size_t)MAXN*FFDIM];
__device__ float    g_er  [RNUM*HEADS];

// ---------------- helpers ----------------
__device__ __forceinline__ float geluf(float v) {
    return 0.5f * v * (1.0f + erff(v * 0.7071067811865475f));
}
__device__ __forceinline__ float eluf(float v) {
    return v > 0.0f ? v : expm1f(v);
}
__device__ __forceinline__ float lreluf(float v) {
    return v > 0.0f ? v : 0.2f * v;
}
__device__ __forceinline__ float tf32r(float v) {
    float o;
    asm("cvt.rna.tf32.f32 %0, %1;" : "=f"(o) : "f"(v));
    return o;
}

// ---------------- init: zero msg + den ----------------
__global__ void init_kernel(int Nn) {
    int i = blockIdx.x * blockDim.x + threadIdx.x;
    if (i < Nn * (HID / 4)) ((float4*)g_msg)[i] = make_float4(0.f,0.f,0.f,0.f);
    if (i < Nn * HEADS) g_den[i] = 0.0f;
}

__global__ void er_kernel(const float* __restrict__ emb,
                          const float* __restrict__ att_edge) {
    int t = threadIdx.x;
    int r = t >> 2, h = t & 3;
    float s = 0.0f;
    #pragma unroll
    for (int d = 0; d < 32; d++)
        s += emb[r * HID + h * 32 + d] * att_edge[h * 32 + d];
    g_er[r * HEADS + h] = s;
}

// w_att[i][c]:  c<32: src dots, col = r*4+h;  32..63: dst;  64..127: zero
__global__ void watt_kernel(const float* __restrict__ weight,
                            const float* __restrict__ att_src,
                            const float* __restrict__ att_dst) {
    int idx = blockIdx.x * blockDim.x + threadIdx.x;
    if (idx >= 128 * 128) return;
    int i = idx >> 7, c = idx & 127;
    float s = 0.0f;
    if (c < 64) {
        const float* vec = (c < 32) ? att_src : att_dst;
        int cc = c & 31;
        int r = cc >> 2, h = cc & 3;
        const float* wrow = weight + (long)r * HID * HID + (long)i * HID + h * 32;
        #pragma unroll
        for (int d = 0; d < 32; d++) s += wrow[d] * vec[h * 32 + d];
    }
    g_wattp[i * 128 + c] = s;
}

// ---------------- layernorm (warp per row, 128 cols) ----------------
__global__ void ln_kernel(const float* __restrict__ x,
                          const float* __restrict__ w,
                          const float* __restrict__ b,
                          float* __restrict__ out, int Nn) {
    int gw = (blockIdx.x * blockDim.x + threadIdx.x) >> 5;
    int lane = threadIdx.x & 31;
    if (gw >= Nn) return;
    const float4 v = *(const float4*)(x + (size_t)gw * HID + lane * 4);
    float s = v.x + v.y + v.z + v.w;
    float q = v.x * v.x + v.y * v.y + v.z * v.z + v.w * v.w;
    #pragma unroll
    for (int o = 16; o; o >>= 1) {
        s += __shfl_xor_sync(0xffffffffu, s, o);
        q += __shfl_xor_sync(0xffffffffu, q, o);
    }
    float mu = s * (1.0f / HID);
    float var = q * (1.0f / HID) - mu * mu;
    float rstd = rsqrtf(var + 1e-5f);
    float4 wv = *(const float4*)(w + lane * 4);
    float4 bv = *(const float4*)(b + lane * 4);
    float4 o4;
    o4.x = (v.x - mu) * rstd * wv.x + bv.x;
    o4.y = (v.y - mu) * rstd * wv.y + bv.y;
    o4.z = (v.z - mu) * rstd * wv.z + bv.z;
    o4.w = (v.w - mu) * rstd * wv.w + bv.w;
    *(float4*)(out + (size_t)gw * HID + lane * 4) = o4;
}

// ---------------- tf32 tensor-core GEMM ----------------
#define APAD 20
#define BPAD 136
__global__ __launch_bounds__(256)
void gemm_tf32(const float* __restrict__ A, const float* __restrict__ B,
               float* __restrict__ C, const float* __restrict__ bias,
               const float* __restrict__ resid,
               int M, int K, int ncols, int act,
               long strideB, long strideC) {
    __shared__ float As[2][128][APAD];
    __shared__ float Bs[2][16][BPAD];

    const float* Bb = B + (long)blockIdx.z * strideB;
    float* Cb = C + (long)blockIdx.z * strideC;
    const int m0 = blockIdx.x * 128;
    const int n0 = blockIdx.y * 128;
    const int tid = threadIdx.x;
    const int wid = tid >> 5, lane = tid & 31;
    const int wm = wid >> 2, wn = wid & 3;
    const int g = lane >> 2, tg = lane & 3;

    float acc[4][4][4];
    #pragma unroll
    for (int i = 0; i < 4; i++)
        #pragma unroll
        for (int j = 0; j < 4; j++)
            #pragma unroll
            for (int c = 0; c < 4; c++) acc[i][j][c] = 0.0f;

    const int la_row0 = tid >> 2, la_q = tid & 3;
    const int lb_c = tid & 31;
    const int nk = K >> 4;

    {
        #pragma unroll
        for (int l = 0; l < 2; l++) {
            int row = la_row0 + l * 64;
            float4 v = make_float4(0.f,0.f,0.f,0.f);
            if (m0 + row < M)
                v = *(const float4*)(A + (long)(m0 + row) * K + la_q * 4);
            As[0][row][la_q*4+0] = tf32r(v.x);
            As[0][row][la_q*4+1] = tf32r(v.y);
            As[0][row][la_q*4+2] = tf32r(v.z);
            As[0][row][la_q*4+3] = tf32r(v.w);
        }
        #pragma unroll
        for (int l = 0; l < 2; l++) {
            int row = (tid >> 5) + l * 8;
            float4 v = *(const float4*)(Bb + (long)row * ncols + n0 + lb_c * 4);
            Bs[0][row][lb_c*4+0] = tf32r(v.x);
            Bs[0][row][lb_c*4+1] = tf32r(v.y);
            Bs[0][row][lb_c*4+2] = tf32r(v.z);
            Bs[0][row][lb_c*4+3] = tf32r(v.w);
        }
    }
    __syncthreads();

    for (int it = 0; it < nk; it++) {
        int buf = it & 1;
        float4 ra[2], rb[2];
        bool have_next = (it + 1 < nk);
        if (have_next) {
            int k0 = (it + 1) << 4;
            #pragma unroll
            for (int l = 0; l < 2; l++) {
                int row = la_row0 + l * 64;
                ra[l] = make_float4(0.f,0.f,0.f,0.f);
                if (m0 + row < M)
                    ra[l] = *(const float4*)(A + (long)(m0 + row) * K + k0 + la_q * 4);
            }
            #pragma unroll
            for (int l = 0; l < 2; l++) {
                int row = (tid >> 5) + l * 8;
                rb[l] = *(const float4*)(Bb + (long)(k0 + row) * ncols + n0 + lb_c * 4);
            }
        }

        #pragma unroll
        for (int kk = 0; kk < 16; kk += 8) {
            unsigned af[4][4];
            #pragma unroll
            for (int tm = 0; tm < 4; tm++) {
                int rb_ = wm * 64 + tm * 16;
                af[tm][0] = __float_as_uint(As[buf][rb_ + g     ][kk + tg    ]);
                af[tm][1] = __float_as_uint(As[buf][rb_ + g + 8 ][kk + tg    ]);
                af[tm][2] = __float_as_uint(As[buf][rb_ + g     ][kk + tg + 4]);
                af[tm][3] = __float_as_uint(As[buf][rb_ + g + 8 ][kk + tg + 4]);
            }
            unsigned bf0[4], bf1[4];
            #pragma unroll
            for (int tn = 0; tn < 4; tn++) {
                int cb = wn * 32 + tn * 8;
                bf0[tn] = __float_as_uint(Bs[buf][kk + tg    ][cb + g]);
                bf1[tn] = __float_as_uint(Bs[buf][kk + tg + 4][cb + g]);
            }
            #pragma unroll
            for (int tm = 0; tm < 4; tm++)
                #pragma unroll
                for (int tn = 0; tn < 4; tn++) {
                    asm volatile(
                        "mma.sync.aligned.m16n8k8.row.col.f32.tf32.tf32.f32 "
                        "{%0,%1,%2,%3}, {%4,%5,%6,%7}, {%8,%9}, {%0,%1,%2,%3};"
                        : "+f"(acc[tm][tn][0]), "+f"(acc[tm][tn][1]),
                          "+f"(acc[tm][tn][2]), "+f"(acc[tm][tn][3])
                        : "r"(af[tm][0]), "r"(af[tm][1]), "r"(af[tm][2]), "r"(af[tm][3]),
                          "r"(bf0[tn]), "r"(bf1[tn]));
                }
        }

        if (have_next) {
            int nb = 1 - buf;
            #pragma unroll
            for (int l = 0; l < 2; l++) {
                int row = la_row0 + l * 64;
                As[nb][row][la_q*4+0] = tf32r(ra[l].x);
                As[nb][row][la_q*4+1] = tf32r(ra[l].y);
                As[nb][row][la_q*4+2] = tf32r(ra[l].z);
                As[nb][row][la_q*4+3] = tf32r(ra[l].w);
            }
            #pragma unroll
            for (int l = 0; l < 2; l++) {
                int row = (tid >> 5) + l * 8;
                Bs[nb][row][lb_c*4+0] = tf32r(rb[l].x);
                Bs[nb][row][lb_c*4+1] = tf32r(rb[l].y);
                Bs[nb][row][lb_c*4+2] = tf32r(rb[l].z);
                Bs[nb][row][lb_c*4+3] = tf32r(rb[l].w);
            }
        }
        __syncthreads();
    }

    #pragma unroll
    for (int tm = 0; tm < 4; tm++) {
        int r0 = m0 + wm * 64 + tm * 16 + g;
        #pragma unroll
        for (int tn = 0; tn < 4; tn++) {
            int col = n0 + wn * 32 + tn * 8 + 2 * tg;
            float2 bv = make_float2(0.f, 0.f);
            if (bias) bv = *(const float2*)(bias + col);
            #pragma unroll
            for (int half = 0; half < 2; half++) {
                int row = r0 + half * 8;
                if (row >= M) continue;
                float v0 = acc[tm][tn][half*2+0] + bv.x;
                float v1 = acc[tm][tn][half*2+1] + bv.y;
                if (act == 1) { v0 = geluf(v0); v1 = geluf(v1); }
                if (resid) {
                    float2 rr = *(const float2*)(resid + (long)row * ncols + col);
                    v0 += rr.x; v1 += rr.y;
                }
                *(float2*)(Cb + (long)row * ncols + col) = make_float2(v0, v1);
            }
        }
    }
}

// ------------- single fused edge pass: logits + exp + den + scatter -------------
// warp per edge. No max-subtraction: logits are O(few), exp is safe in fp32,
// softmax ratio is shift-invariant.
__global__ void edge_pass(const int* __restrict__ ei, const int* __restrict__ et,
                          int E, int Nn) {
    long gw = ((long)blockIdx.x * blockDim.x + threadIdx.x) >> 5;
    int lane = threadIdx.x & 31;
    if (gw >= E) return;
    int r = et[gw];
    int s = ei[gw];
    int d = ei[E + gw];
    int h = lane >> 3;
    float asrc = g_ad[(long)s * 128 + r * 4 + h];
    float adst = g_ad[(long)d * 128 + 32 + r * 4 + h];
    float er   = g_er[r * HEADS + h];
    float ex = __expf(lreluf(asrc + adst + er));
    if ((lane & 7) == 0) atomicAdd(g_den + (long)d * HEADS + h, ex);
    float4 xs = *(const float4*)(g_xr + ((long)r * Nn + s) * HID + lane * 4);
    float* o = g_msg + (long)d * HID + lane * 4;
    asm volatile("red.global.add.v4.f32 [%0], {%1,%2,%3,%4};"
                 :: "l"(o), "f"(xs.x * ex), "f"(xs.y * ex),
                    "f"(xs.z * ex), "f"(xs.w * ex)
                 : "memory");
}

// ---------------- post: normalize + root + elu + residual + LN2 ----------------
__global__ void post_kernel(const float* __restrict__ x,
                            const float* __restrict__ w,
                            const float* __restrict__ b,
                            float* __restrict__ x1out, int Nn) {
    int gw = (blockIdx.x * blockDim.x + threadIdx.x) >> 5;
    int lane = threadIdx.x & 31;
    if (gw >= Nn) return;
    int h = lane >> 3;
    float den = g_den[(long)gw * HEADS + h];
    float inv = 1.0f / (den + 1e-16f);
    float4 mg = *(const float4*)(g_msg + (size_t)gw * HID + lane * 4);
    float4 rt = *(const float4*)(g_outc + (size_t)gw * HID + lane * 4);
    float4 oc;
    oc.x = eluf(mg.x * inv + rt.x);
    oc.y = eluf(mg.y * inv + rt.y);
    oc.z = eluf(mg.z * inv + rt.z);
    oc.w = eluf(mg.w * inv + rt.w);
    float4 xv = *(const float4*)(x + (size_t)gw * HID + lane * 4);
    float4 x1 = make_float4(xv.x + oc.x, xv.y + oc.y, xv.z + oc.z, xv.w + oc.w);
    *(float4*)(x1out + (size_t)gw * HID + lane * 4) = x1;
    float s = x1.x + x1.y + x1.z + x1.w;
    float q = x1.x * x1.x + x1.y * x1.y + x1.z * x1.z + x1.w * x1.w;
    #pragma unroll
    for (int o = 16; o; o >>= 1) {
        s += __shfl_xor_sync(0xffffffffu, s, o);
        q += __shfl_xor_sync(0xffffffffu, q, o);
    }
    float mu = s * (1.0f / HID);
    float var = q * (1.0f / HID) - mu * mu;
    float rstd = rsqrtf(var + 1e-5f);
    float4 wv = *(const float4*)(w + lane * 4);
    float4 bv = *(const float4*)(b + lane * 4);
    float4 o4;
    o4.x = (x1.x - mu) * rstd * wv.x + bv.x;
    o4.y = (x1.y - mu) * rstd * wv.y + bv.y;
    o4.z = (x1.z - mu) * rstd * wv.z + bv.z;
    o4.w = (x1.w - mu) * rstd * wv.w + bv.w;
    *(float4*)(g_h2 + (size_t)gw * HID + lane * 4) = o4;
}

// ---------------- launch ----------------
extern "C" void kernel_launch(void* const* d_in, const int* in_sizes, int n_in,
                              void* d_out, int out_size) {
    const float* x          = (const float*)d_in[0];
    const float* weight     = (const float*)d_in[1];
    const float* root_w     = (const float*)d_in[2];
    const float* edge_emb   = (const float*)d_in[3];
    const float* att_src    = (const float*)d_in[4];
    const float* att_dst    = (const float*)d_in[5];
    const float* att_edge   = (const float*)d_in[6];
    const float* bias       = (const float*)d_in[7];
    const float* n1w        = (const float*)d_in[8];
    const float* n1b        = (const float*)d_in[9];
    const float* n2w        = (const float*)d_in[10];
    const float* n2b        = (const float*)d_in[11];
    const float* ffn_w1     = (const float*)d_in[12];
    const float* ffn_b1     = (const float*)d_in[13];
    const float* ffn_w2     = (const float*)d_in[14];
    const float* ffn_b2     = (const float*)d_in[15];
    const int*   edge_index = (const int*)d_in[16];
    const int*   edge_type  = (const int*)d_in[17];
    float* out = (float*)d_out;

    int N = in_sizes[0] / HID;
    int E = in_sizes[17];
    int R = in_sizes[1] / (HID * HID);

    float *p_h1, *p_xr, *p_ad, *p_wattp, *p_outc, *p_h2, *p_t;
    cudaGetSymbolAddress((void**)&p_h1,    g_h1);
    cudaGetSymbolAddress((void**)&p_xr,    g_xr);
    cudaGetSymbolAddress((void**)&p_ad,    g_ad);
    cudaGetSymbolAddress((void**)&p_wattp, g_wattp);
    cudaGetSymbolAddress((void**)&p_outc,  g_outc);
    cudaGetSymbolAddress((void**)&p_h2,    g_h2);
    cudaGetSymbolAddress((void**)&p_t,     g_t);

    int rowBlocks = (N + 7) / 8;
    int mTiles    = (N + 127) / 128;

    init_kernel<<<(N * HID / 4 + 255) / 256, 256>>>(N);
    er_kernel<<<1, 32>>>(edge_emb, att_edge);
    watt_kernel<<<64, 256>>>(weight, att_src, att_dst);
    ln_kernel<<<rowBlocks, 256>>>(x, n1w, n1b, p_h1, N);

    // attention dots via small GEMM: g_ad = h1 @ w_att (padded to 128 cols)
    gemm_tf32<<<dim3(mTiles, 1, 1), 256>>>(p_h1, p_wattp, p_ad, nullptr, nullptr,
                                           N, HID, 128, 0, 0, 0);
    // relation-wise projection: x_r[r] = h1 @ weight[r]
    gemm_tf32<<<dim3(mTiles, 1, R), 256>>>(p_h1, weight, p_xr, nullptr, nullptr,
                                           N, HID, HID, 0,
                                           (long)HID * HID, (long)N * HID);
    // root term (+bias) into its own buffer
    gemm_tf32<<<dim3(mTiles, 1, 1), 256>>>(p_h1, root_w, p_outc, bias, nullptr,
                                           N, HID, HID, 0, 0, 0);

    // ONE fused edge pass: logits + exp + den + message scatter
    edge_pass<<<(E + 7) / 8, 256>>>(edge_index, edge_type, E, N);

    post_kernel<<<rowBlocks, 256>>>(x, n2w, n2b, out, N);

    gemm_tf32<<<dim3(mTiles, 4, 1), 256>>>(p_h2, ffn_w1, p_t, ffn_b1, nullptr,
                                           N, HID, FFDIM, 1, 0, 0);
    gemm_tf32<<<dim3(mTiles, 1, 1), 256>>>(p_t, ffn_w2, out, ffn_b2, out,
                                           N, FFDIM, HID, 0, 0, 0);
}

// round 5
// speedup vs baseline: 1.5597x; 1.2196x over previous
#include <cuda_runtime.h>
#include <cuda_fp16.h>
#include <math.h>

#define HID   128
#define MAXN  50000
#define MAXE  800000
#define RNUM  8
#define HEADS 4
#define FFDIM 512

// ---------------- scratch (device globals: allocation-free rule) ----------------
__device__ float    g_h1  [(size_t)MAXN*HID];
__device__ __half   g_xr  [(size_t)RNUM*MAXN*HID];  // fp16 relation projections
__device__ float    g_ad  [(size_t)MAXN*128];       // per-node attn dots
__device__ float    g_wattp[128*128];
__device__ float    g_den [(size_t)MAXN*HEADS];
__device__ float    g_msg [(size_t)MAXN*HID];
__device__ float    g_outc[(size_t)MAXN*HID];
__device__ float    g_h2  [(size_t)MAXN*HID];
__device__ float    g_t   [(size_t)MAXN*FFDIM];
__device__ float    g_er  [RNUM*HEADS];

// ---------------- helpers ----------------
__device__ __forceinline__ float geluf(float v) {
    return 0.5f * v * (1.0f + erff(v * 0.7071067811865475f));
}
__device__ __forceinline__ float eluf(float v) {
    return v > 0.0f ? v : expm1f(v);
}
__device__ __forceinline__ float lreluf(float v) {
    return v > 0.0f ? v : 0.2f * v;
}

// ---------------- init ----------------
__global__ void init_kernel(int Nn) {
    int i = blockIdx.x * blockDim.x + threadIdx.x;
    if (i < Nn * (HID / 4)) ((float4*)g_msg)[i] = make_float4(0.f,0.f,0.f,0.f);
    if (i < Nn * HEADS) g_den[i] = 0.0f;
}

__global__ void er_kernel(const float* __restrict__ emb,
                          const float* __restrict__ att_edge) {
    int t = threadIdx.x;
    int r = t >> 2, h = t & 3;
    float s = 0.0f;
    #pragma unroll
    for (int d = 0; d < 32; d++)
        s += emb[r * HID + h * 32 + d] * att_edge[h * 32 + d];
    g_er[r * HEADS + h] = s;
}

__global__ void watt_kernel(const float* __restrict__ weight,
                            const float* __restrict__ att_src,
                            const float* __restrict__ att_dst) {
    int idx = blockIdx.x * blockDim.x + threadIdx.x;
    if (idx >= 128 * 128) return;
    int i = idx >> 7, c = idx & 127;
    float s = 0.0f;
    if (c < 64) {
        const float* vec = (c < 32) ? att_src : att_dst;
        int cc = c & 31;
        int r = cc >> 2, h = cc & 3;
        const float* wrow = weight + (long)r * HID * HID + (long)i * HID + h * 32;
        #pragma unroll
        for (int d = 0; d < 32; d++) s += wrow[d] * vec[h * 32 + d];
    }
    g_wattp[i * 128 + c] = s;
}

// ---------------- layernorm (warp per row) ----------------
__global__ void ln_kernel(const float* __restrict__ x,
                          const float* __restrict__ w,
                          const float* __restrict__ b,
                          float* __restrict__ out, int Nn) {
    int gw = (blockIdx.x * blockDim.x + threadIdx.x) >> 5;
    int lane = threadIdx.x & 31;
    if (gw >= Nn) return;
    const float4 v = *(const float4*)(x + (size_t)gw * HID + lane * 4);
    float s = v.x + v.y + v.z + v.w;
    float q = v.x * v.x + v.y * v.y + v.z * v.z + v.w * v.w;
    #pragma unroll
    for (int o = 16; o; o >>= 1) {
        s += __shfl_xor_sync(0xffffffffu, s, o);
        q += __shfl_xor_sync(0xffffffffu, q, o);
    }
    float mu = s * (1.0f / HID);
    float var = q * (1.0f / HID) - mu * mu;
    float rstd = rsqrtf(var + 1e-5f);
    float4 wv = *(const float4*)(w + lane * 4);
    float4 bv = *(const float4*)(b + lane * 4);
    float4 o4;
    o4.x = (v.x - mu) * rstd * wv.x + bv.x;
    o4.y = (v.y - mu) * rstd * wv.y + bv.y;
    o4.z = (v.z - mu) * rstd * wv.z + bv.z;
    o4.w = (v.w - mu) * rstd * wv.w + bv.w;
    *(float4*)(out + (size_t)gw * HID + lane * 4) = o4;
}

// ---------------- fp16 tensor-core GEMM (ldmatrix + m16n8k16) -------------------
// BM=128, BN=128, K chunked by 128. 256 threads = 8 warps (2x4), warp tile 64x32.
// SMEM: As[128][136] halves, Bs[128][136] halves (both row-major, [row][k]/[k][n]).
#define SROW 136
#define SMEM_BYTES (2 * 128 * SROW * 2)

__global__ __launch_bounds__(256, 2)
void gemm_f16(const float* __restrict__ A, const float* __restrict__ B,
              void* __restrict__ C, const float* __restrict__ bias,
              const float* __restrict__ resid,
              int M, int K, int ncols, int act, int outHalf,
              long strideB, long strideC) {
    extern __shared__ __half sm[];
    __half* As = sm;                 // [128][SROW]  row m, col k
    __half* Bs = sm + 128 * SROW;    // [128][SROW]  row k, col n

    const float* Bb = B + (long)blockIdx.z * strideB;
    const int m0 = blockIdx.x * 128;
    const int n0 = blockIdx.y * 128;
    const int tid = threadIdx.x;
    const int lane = tid & 31, wid = tid >> 5;
    const int wm = wid >> 2, wn = wid & 3;
    const int g = lane >> 2, tg = lane & 3;

    float acc[4][4][4];
    #pragma unroll
    for (int i = 0; i < 4; i++)
        #pragma unroll
        for (int j = 0; j < 4; j++)
            #pragma unroll
            for (int c = 0; c < 4; c++) acc[i][j][c] = 0.0f;

    // ldmatrix per-lane source addresses (half-element offsets)
    unsigned as_base = (unsigned)__cvta_generic_to_shared(As);
    unsigned bs_base = (unsigned)__cvta_generic_to_shared(Bs);
    const int a_row = (lane & 15);            // row within 16-row block
    const int a_koff = (lane >> 4) << 3;      // 0 or 8 (k halves)
    const int b_krow = (lane & 15);           // k row within 16

    const int ld_row = tid >> 5;              // loader: 8 rows per pass? no:
    // loader mapping: idx = tid + l*256; row = idx>>5 (32 float4 per 128-col row)

    for (int k0 = 0; k0 < K; k0 += 128) {
        if (k0) __syncthreads();
        // load A chunk: rows of A [M][K], cols k0..k0+127
        #pragma unroll
        for (int l = 0; l < 16; l++) {
            int idx = tid + l * 256;
            int row = idx >> 5, q = idx & 31;
            float4 v = make_float4(0.f,0.f,0.f,0.f);
            if (m0 + row < M)
                v = *(const float4*)(A + (long)(m0 + row) * K + k0 + q * 4);
            __half2 h01 = __floats2half2_rn(v.x, v.y);
            __half2 h23 = __floats2half2_rn(v.z, v.w);
            *(uint2*)&As[row * SROW + q * 4] =
                make_uint2(*(unsigned*)&h01, *(unsigned*)&h23);
        }
        // load B chunk: B [K][ncols], rows k0..k0+127, cols n0..n0+127
        #pragma unroll
        for (int l = 0; l < 16; l++) {
            int idx = tid + l * 256;
            int row = idx >> 5, q = idx & 31;
            float4 v = *(const float4*)(Bb + (long)(k0 + row) * ncols + n0 + q * 4);
            __half2 h01 = __floats2half2_rn(v.x, v.y);
            __half2 h23 = __floats2half2_rn(v.z, v.w);
            *(uint2*)&Bs[row * SROW + q * 4] =
                make_uint2(*(unsigned*)&h01, *(unsigned*)&h23);
        }
        __syncthreads();

        #pragma unroll
        for (int kk = 0; kk < 8; kk++) {
            const int k16 = kk * 16;
            unsigned af[4][4], bf[4][2];
            #pragma unroll
            for (int tm = 0; tm < 4; tm++) {
                int rb = wm * 64 + tm * 16;
                unsigned addr = as_base +
                    (((rb + a_row) * SROW + k16 + a_koff) << 1);
                asm volatile(
                    "ldmatrix.sync.aligned.m8n8.x4.shared.b16 {%0,%1,%2,%3}, [%4];"
                    : "=r"(af[tm][0]), "=r"(af[tm][1]),
                      "=r"(af[tm][2]), "=r"(af[tm][3])
                    : "r"(addr));
            }
            #pragma unroll
            for (int tn = 0; tn < 4; tn++) {
                int cb = wn * 32 + tn * 8;
                unsigned addr = bs_base +
                    (((k16 + b_krow) * SROW + cb) << 1);
                asm volatile(
                    "ldmatrix.sync.aligned.m8n8.x2.trans.shared.b16 {%0,%1}, [%2];"
                    : "=r"(bf[tn][0]), "=r"(bf[tn][1])
                    : "r"(addr));
            }
            #pragma unroll
            for (int tm = 0; tm < 4; tm++)
                #pragma unroll
                for (int tn = 0; tn < 4; tn++) {
                    asm volatile(
                        "mma.sync.aligned.m16n8k16.row.col.f32.f16.f16.f32 "
                        "{%0,%1,%2,%3}, {%4,%5,%6,%7}, {%8,%9}, {%0,%1,%2,%3};"
                        : "+f"(acc[tm][tn][0]), "+f"(acc[tm][tn][1]),
                          "+f"(acc[tm][tn][2]), "+f"(acc[tm][tn][3])
                        : "r"(af[tm][0]), "r"(af[tm][1]),
                          "r"(af[tm][2]), "r"(af[tm][3]),
                          "r"(bf[tn][0]), "r"(bf[tn][1]));
                }
        }
    }

    // ---- epilogue ----
    #pragma unroll
    for (int tm = 0; tm < 4; tm++) {
        int r0 = m0 + wm * 64 + tm * 16 + g;
        #pragma unroll
        for (int tn = 0; tn < 4; tn++) {
            int col = n0 + wn * 32 + tn * 8 + 2 * tg;
            float2 bv = make_float2(0.f, 0.f);
            if (bias) bv = *(const float2*)(bias + col);
            #pragma unroll
            for (int half_ = 0; half_ < 2; half_++) {
                int row = r0 + half_ * 8;
                if (row >= M) continue;
                float v0 = acc[tm][tn][half_*2+0] + bv.x;
                float v1 = acc[tm][tn][half_*2+1] + bv.y;
                if (act == 1) { v0 = geluf(v0); v1 = geluf(v1); }
                if (resid) {
                    float2 rr = *(const float2*)(resid + (long)row * ncols + col);
                    v0 += rr.x; v1 += rr.y;
                }
                if (outHalf) {
                    __half* Ch = (__half*)C + blockIdx.z * strideC;
                    __half2 hv = __floats2half2_rn(v0, v1);
                    *(__half2*)(Ch + (long)row * ncols + col) = hv;
                } else {
                    float* Cf = (float*)C + blockIdx.z * strideC;
                    *(float2*)(Cf + (long)row * ncols + col) = make_float2(v0, v1);
                }
            }
        }
    }
}

// ------------- single fused edge pass: logits + exp + den + scatter -------------
__global__ void edge_pass(const int* __restrict__ ei, const int* __restrict__ et,
                          int E, int Nn) {
    long gw = ((long)blockIdx.x * blockDim.x + threadIdx.x) >> 5;
    int lane = threadIdx.x & 31;
    if (gw >= E) return;
    int r = et[gw];
    int s = ei[gw];
    int d = ei[E + gw];
    int h = lane >> 3;
    float asrc = g_ad[(long)s * 128 + r * 4 + h];
    float adst = g_ad[(long)d * 128 + 32 + r * 4 + h];
    float er   = g_er[r * HEADS + h];
    float ex = __expf(lreluf(asrc + adst + er));
    if ((lane & 7) == 0) atomicAdd(g_den + (long)d * HEADS + h, ex);
    uint2 raw = *(const uint2*)(g_xr + ((long)r * Nn + s) * HID + lane * 4);
    float2 x01 = __half22float2(*(__half2*)&raw.x);
    float2 x23 = __half22float2(*(__half2*)&raw.y);
    float* o = g_msg + (long)d * HID + lane * 4;
    asm volatile("red.global.add.v4.f32 [%0], {%1,%2,%3,%4};"
                 :: "l"(o), "f"(x01.x * ex), "f"(x01.y * ex),
                    "f"(x23.x * ex), "f"(x23.y * ex)
                 : "memory");
}

// ---------------- post: normalize + root + elu + residual + LN2 ----------------
__global__ void post_kernel(const float* __restrict__ x,
                            const float* __restrict__ w,
                            const float* __restrict__ b,
                            float* __restrict__ x1out, int Nn) {
    int gw = (blockIdx.x * blockDim.x + threadIdx.x) >> 5;
    int lane = threadIdx.x & 31;
    if (gw >= Nn) return;
    int h = lane >> 3;
    float den = g_den[(long)gw * HEADS + h];
    float inv = 1.0f / (den + 1e-16f);
    float4 mg = *(const float4*)(g_msg + (size_t)gw * HID + lane * 4);
    float4 rt = *(const float4*)(g_outc + (size_t)gw * HID + lane * 4);
    float4 oc;
    oc.x = eluf(mg.x * inv + rt.x);
    oc.y = eluf(mg.y * inv + rt.y);
    oc.z = eluf(mg.z * inv + rt.z);
    oc.w = eluf(mg.w * inv + rt.w);
    float4 xv = *(const float4*)(x + (size_t)gw * HID + lane * 4);
    float4 x1 = make_float4(xv.x + oc.x, xv.y + oc.y, xv.z + oc.z, xv.w + oc.w);
    *(float4*)(x1out + (size_t)gw * HID + lane * 4) = x1;
    float s = x1.x + x1.y + x1.z + x1.w;
    float q = x1.x * x1.x + x1.y * x1.y + x1.z * x1.z + x1.w * x1.w;
    #pragma unroll
    for (int o = 16; o; o >>= 1) {
        s += __shfl_xor_sync(0xffffffffu, s, o);
        q += __shfl_xor_sync(0xffffffffu, q, o);
    }
    float mu = s * (1.0f / HID);
    float var = q * (1.0f / HID) - mu * mu;
    float rstd = rsqrtf(var + 1e-5f);
    float4 wv = *(const float4*)(w + lane * 4);
    float4 bv = *(const float4*)(b + lane * 4);
    float4 o4;
    o4.x = (x1.x - mu) * rstd * wv.x + bv.x;
    o4.y = (x1.y - mu) * rstd * wv.y + bv.y;
    o4.z = (x1.z - mu) * rstd * wv.z + bv.z;
    o4.w = (x1.w - mu) * rstd * wv.w + bv.w;
    *(float4*)(g_h2 + (size_t)gw * HID + lane * 4) = o4;
}

// ---------------- launch ----------------
extern "C" void kernel_launch(void* const* d_in, const int* in_sizes, int n_in,
                              void* d_out, int out_size) {
    const float* x          = (const float*)d_in[0];
    const float* weight     = (const float*)d_in[1];
    const float* root_w     = (const float*)d_in[2];
    const float* edge_emb   = (const float*)d_in[3];
    const float* att_src    = (const float*)d_in[4];
    const float* att_dst    = (const float*)d_in[5];
    const float* att_edge   = (const float*)d_in[6];
    const float* bias       = (const float*)d_in[7];
    const float* n1w        = (const float*)d_in[8];
    const float* n1b        = (const float*)d_in[9];
    const float* n2w        = (const float*)d_in[10];
    const float* n2b        = (const float*)d_in[11];
    const float* ffn_w1     = (const float*)d_in[12];
    const float* ffn_b1     = (const float*)d_in[13];
    const float* ffn_w2     = (const float*)d_in[14];
    const float* ffn_b2     = (const float*)d_in[15];
    const int*   edge_index = (const int*)d_in[16];
    const int*   edge_type  = (const int*)d_in[17];
    float* out = (float*)d_out;

    int N = in_sizes[0] / HID;
    int E = in_sizes[17];
    int R = in_sizes[1] / (HID * HID);

    static int smem_set = 0;
    if (!smem_set) {
        cudaFuncSetAttribute(gemm_f16,
            cudaFuncAttributeMaxDynamicSharedMemorySize, SMEM_BYTES);
        smem_set = 1;
    }

    float *p_h1, *p_ad, *p_wattp, *p_outc, *p_h2, *p_t;
    __half* p_xr;
    cudaGetSymbolAddress((void**)&p_h1,    g_h1);
    cudaGetSymbolAddress((void**)&p_xr,    g_xr);
    cudaGetSymbolAddress((void**)&p_ad,    g_ad);
    cudaGetSymbolAddress((void**)&p_wattp, g_wattp);
    cudaGetSymbolAddress((void**)&p_outc,  g_outc);
    cudaGetSymbolAddress((void**)&p_h2,    g_h2);
    cudaGetSymbolAddress((void**)&p_t,     g_t);

    int rowBlocks = (N + 7) / 8;
    int mTiles    = (N + 127) / 128;

    init_kernel<<<(N * HID / 4 + 255) / 256, 256>>>(N);
    er_kernel<<<1, 32>>>(edge_emb, att_edge);
    watt_kernel<<<64, 256>>>(weight, att_src, att_dst);
    ln_kernel<<<rowBlocks, 256>>>(x, n1w, n1b, p_h1, N);

    // attention dots: g_ad = h1 @ w_att (fp32 out)
    gemm_f16<<<dim3(mTiles, 1, 1), 256, SMEM_BYTES>>>(
        p_h1, p_wattp, p_ad, nullptr, nullptr, N, HID, 128, 0, 0, 0, 0);
    // relation projections: g_xr[r] = h1 @ weight[r]  (fp16 out)
    gemm_f16<<<dim3(mTiles, 1, R), 256, SMEM_BYTES>>>(
        p_h1, weight, p_xr, nullptr, nullptr, N, HID, HID, 0, 1,
        (long)HID * HID, (long)N * HID);
    // root term (+bias)
    gemm_f16<<<dim3(mTiles, 1, 1), 256, SMEM_BYTES>>>(
        p_h1, root_w, p_outc, bias, nullptr, N, HID, HID, 0, 0, 0, 0);

    // fused edge pass
    edge_pass<<<(E + 7) / 8, 256>>>(edge_index, edge_type, E, N);

    post_kernel<<<rowBlocks, 256>>>(x, n2w, n2b, out, N);

    // FFN
    gemm_f16<<<dim3(mTiles, 4, 1), 256, SMEM_BYTES>>>(
        p_h2, ffn_w1, p_t, ffn_b1, nullptr, N, HID, FFDIM, 1, 0, 0, 0);
    gemm_f16<<<dim3(mTiles, 1, 1), 256, SMEM_BYTES>>>(
        p_t, ffn_w2, out, ffn_b2, out, N, FFDIM, HID, 0, 0, 0, 0);
}

// round 7
// speedup vs baseline: 1.8001x; 1.1541x over previous
#include <cuda_runtime.h>
#include <cuda_fp16.h>
#include <math.h>

#define HID   128
#define MAXN  50000
#define MAXE  800000
#define RNUM  8
#define HEADS 4
#define FFDIM 512

// ---------------- scratch (device globals: allocation-free rule) ----------------
__device__ __half   g_h1  [(size_t)MAXN*HID];       // LN1(x), fp16
__device__ __half   g_xr  [(size_t)RNUM*MAXN*HID];  // relation projections, fp16
__device__ float    g_ad  [(size_t)MAXN*128];       // per-node attn dots
__device__ float    g_wattp[128*128];
__device__ float    g_den [(size_t)MAXN*HEADS];
__device__ float    g_msg [(size_t)MAXN*HID];
__device__ float    g_outc[(size_t)MAXN*HID];
__device__ __half   g_h2  [(size_t)MAXN*HID];       // LN2 out, fp16
__device__ __half   g_t   [(size_t)MAXN*FFDIM];     // FFN hidden, fp16
__device__ float    g_er  [RNUM*HEADS];

// ---------------- helpers ----------------
__device__ __forceinline__ float geluf(float v) {
    return 0.5f * v * (1.0f + erff(v * 0.7071067811865475f));
}
__device__ __forceinline__ float eluf(float v) {
    return v > 0.0f ? v : expm1f(v);
}
__device__ __forceinline__ float lreluf(float v) {
    return v > 0.0f ? v : 0.2f * v;
}

// ---------------- init ----------------
__global__ void init_kernel(int Nn) {
    int i = blockIdx.x * blockDim.x + threadIdx.x;
    if (i < Nn * (HID / 4)) ((float4*)g_msg)[i] = make_float4(0.f,0.f,0.f,0.f);
    if (i < Nn * HEADS) g_den[i] = 0.0f;
}

__global__ void er_kernel(const float* __restrict__ emb,
                          const float* __restrict__ att_edge) {
    int t = threadIdx.x;
    int r = t >> 2, h = t & 3;
    float s = 0.0f;
    #pragma unroll
    for (int d = 0; d < 32; d++)
        s += emb[r * HID + h * 32 + d] * att_edge[h * 32 + d];
    g_er[r * HEADS + h] = s;
}

__global__ void watt_kernel(const float* __restrict__ weight,
                            const float* __restrict__ att_src,
                            const float* __restrict__ att_dst) {
    int idx = blockIdx.x * blockDim.x + threadIdx.x;
    if (idx >= 128 * 128) return;
    int i = idx >> 7, c = idx & 127;
    float s = 0.0f;
    if (c < 64) {
        const float* vec = (c < 32) ? att_src : att_dst;
        int cc = c & 31;
        int r = cc >> 2, h = cc & 3;
        const float* wrow = weight + (long)r * HID * HID + (long)i * HID + h * 32;
        #pragma unroll
        for (int d = 0; d < 32; d++) s += wrow[d] * vec[h * 32 + d];
    }
    g_wattp[i * 128 + c] = s;
}

// ---------------- layernorm (warp per row) -> fp16 out ----------------
__global__ void ln_kernel(const float* __restrict__ x,
                          const float* __restrict__ w,
                          const float* __restrict__ b,
                          __half* __restrict__ out, int Nn) {
    int gw = (blockIdx.x * blockDim.x + threadIdx.x) >> 5;
    int lane = threadIdx.x & 31;
    if (gw >= Nn) return;
    const float4 v = *(const float4*)(x + (size_t)gw * HID + lane * 4);
    float s = v.x + v.y + v.z + v.w;
    float q = v.x * v.x + v.y * v.y + v.z * v.z + v.w * v.w;
    #pragma unroll
    for (int o = 16; o; o >>= 1) {
        s += __shfl_xor_sync(0xffffffffu, s, o);
        q += __shfl_xor_sync(0xffffffffu, q, o);
    }
    float mu = s * (1.0f / HID);
    float var = q * (1.0f / HID) - mu * mu;
    float rstd = rsqrtf(var + 1e-5f);
    float4 wv = *(const float4*)(w + lane * 4);
    float4 bv = *(const float4*)(b + lane * 4);
    __half2 o01 = __floats2half2_rn((v.x - mu) * rstd * wv.x + bv.x,
                                    (v.y - mu) * rstd * wv.y + bv.y);
    __half2 o23 = __floats2half2_rn((v.z - mu) * rstd * wv.z + bv.z,
                                    (v.w - mu) * rstd * wv.w + bv.w);
    *(uint2*)(out + (size_t)gw * HID + lane * 4) =
        make_uint2(*(unsigned*)&o01, *(unsigned*)&o23);
}

// ---------------- fp16 tensor-core GEMM (cp.async A + ldmatrix + m16n8k16) ------
// A fp16 [M][K], B fp32 [K][ncols]. BM=BN=128, K chunked by 128.
#define SROW 136
#define SMEM_BYTES (2 * 128 * SROW * 2)

__global__ __launch_bounds__(256, 2)
void gemm_f16(const __half* __restrict__ A, const float* __restrict__ B,
              void* __restrict__ C, const float* __restrict__ bias,
              const float* __restrict__ resid,
              int M, int K, int ncols, int act, int outHalf,
              long strideB, long strideC) {
    extern __shared__ __half sm[];
    __half* As = sm;                 // [128][SROW]  row m, col k
    __half* Bs = sm + 128 * SROW;    // [128][SROW]  row k, col n

    const float* Bb = B + (long)blockIdx.z * strideB;
    const int m0 = blockIdx.x * 128;
    const int n0 = blockIdx.y * 128;
    const int tid = threadIdx.x;
    const int lane = tid & 31, wid = tid >> 5;
    const int wm = wid >> 2, wn = wid & 3;
    const int g = lane >> 2, tg = lane & 3;

    float acc[4][4][4];
    #pragma unroll
    for (int i = 0; i < 4; i++)
        #pragma unroll
        for (int j = 0; j < 4; j++)
            #pragma unroll
            for (int c = 0; c < 4; c++) acc[i][j][c] = 0.0f;

    unsigned as_base = (unsigned)__cvta_generic_to_shared(As);
    unsigned bs_base = (unsigned)__cvta_generic_to_shared(Bs);
    const int a_row = (lane & 15);
    const int a_koff = (lane >> 4) << 3;
    const int b_krow = (lane & 15);

    for (int k0 = 0; k0 < K; k0 += 128) {
        if (k0) __syncthreads();
        // A chunk via cp.async: 128 rows x 16 copies of 16B; 8 per thread.
        // row = idx>>4 in [0,128), q = idx&15 -> halves q*8 in [0,128)
        #pragma unroll
        for (int l = 0; l < 8; l++) {
            int idx = tid + l * 256;
            int row = idx >> 4, q = idx & 15;
            bool ok = (m0 + row < M);
            const __half* src = A + (ok ? ((long)(m0 + row) * K + k0 + q * 8) : 0);
            unsigned dst = as_base + ((unsigned)(row * SROW + q * 8) << 1);
            int sz = ok ? 16 : 0;
            asm volatile("cp.async.ca.shared.global [%0], [%1], 16, %2;"
                         :: "r"(dst), "l"(src), "r"(sz));
        }
        asm volatile("cp.async.commit_group;");
        // B chunk: fp32 LDG -> cvt -> STS
        #pragma unroll
        for (int l = 0; l < 16; l++) {
            int idx = tid + l * 256;
            int row = idx >> 5, q = idx & 31;
            float4 v = *(const float4*)(Bb + (long)(k0 + row) * ncols + n0 + q * 4);
            __half2 h01 = __floats2half2_rn(v.x, v.y);
            __half2 h23 = __floats2half2_rn(v.z, v.w);
            *(uint2*)&Bs[row * SROW + q * 4] =
                make_uint2(*(unsigned*)&h01, *(unsigned*)&h23);
        }
        asm volatile("cp.async.wait_group 0;");
        __syncthreads();

        #pragma unroll
        for (int kk = 0; kk < 8; kk++) {
            const int k16 = kk * 16;
            unsigned af[4][4], bf[4][2];
            #pragma unroll
            for (int tm = 0; tm < 4; tm++) {
                int rb = wm * 64 + tm * 16;
                unsigned addr = as_base +
                    (((rb + a_row) * SROW + k16 + a_koff) << 1);
                asm volatile(
                    "ldmatrix.sync.aligned.m8n8.x4.shared.b16 {%0,%1,%2,%3}, [%4];"
                    : "=r"(af[tm][0]), "=r"(af[tm][1]),
                      "=r"(af[tm][2]), "=r"(af[tm][3])
                    : "r"(addr));
            }
            #pragma unroll
            for (int tn = 0; tn < 4; tn++) {
                int cb = wn * 32 + tn * 8;
                unsigned addr = bs_base +
                    (((k16 + b_krow) * SROW + cb) << 1);
                asm volatile(
                    "ldmatrix.sync.aligned.m8n8.x2.trans.shared.b16 {%0,%1}, [%2];"
                    : "=r"(bf[tn][0]), "=r"(bf[tn][1])
                    : "r"(addr));
            }
            #pragma unroll
            for (int tm = 0; tm < 4; tm++)
                #pragma unroll
                for (int tn = 0; tn < 4; tn++) {
                    asm volatile(
                        "mma.sync.aligned.m16n8k16.row.col.f32.f16.f16.f32 "
                        "{%0,%1,%2,%3}, {%4,%5,%6,%7}, {%8,%9}, {%0,%1,%2,%3};"
                        : "+f"(acc[tm][tn][0]), "+f"(acc[tm][tn][1]),
                          "+f"(acc[tm][tn][2]), "+f"(acc[tm][tn][3])
                        : "r"(af[tm][0]), "r"(af[tm][1]),
                          "r"(af[tm][2]), "r"(af[tm][3]),
                          "r"(bf[tn][0]), "r"(bf[tn][1]));
                }
        }
    }

    // ---- epilogue ----
    #pragma unroll
    for (int tm = 0; tm < 4; tm++) {
        int r0 = m0 + wm * 64 + tm * 16 + g;
        #pragma unroll
        for (int tn = 0; tn < 4; tn++) {
            int col = n0 + wn * 32 + tn * 8 + 2 * tg;
            float2 bv = make_float2(0.f, 0.f);
            if (bias) bv = *(const float2*)(bias + col);
            #pragma unroll
            for (int half_ = 0; half_ < 2; half_++) {
                int row = r0 + half_ * 8;
                if (row >= M) continue;
                float v0 = acc[tm][tn][half_*2+0] + bv.x;
                float v1 = acc[tm][tn][half_*2+1] + bv.y;
                if (act == 1) { v0 = geluf(v0); v1 = geluf(v1); }
                if (resid) {
                    float2 rr = *(const float2*)(resid + (long)row * ncols + col);
                    v0 += rr.x; v1 += rr.y;
                }
                if (outHalf) {
                    __half* Ch = (__half*)C + blockIdx.z * strideC;
                    __half2 hv = __floats2half2_rn(v0, v1);
                    *(__half2*)(Ch + (long)row * ncols + col) = hv;
                } else {
                    float* Cf = (float*)C + blockIdx.z * strideC;
                    *(float2*)(Cf + (long)row * ncols + col) = make_float2(v0, v1);
                }
            }
        }
    }
}

// ------------- single fused edge pass: logits + exp + den + scatter -------------
__global__ void edge_pass(const int* __restrict__ ei, const int* __restrict__ et,
                          int E, int Nn) {
    long gw = ((long)blockIdx.x * blockDim.x + threadIdx.x) >> 5;
    int lane = threadIdx.x & 31;
    if (gw >= E) return;
    int r = et[gw];
    int s = ei[gw];
    int d = ei[E + gw];
    int h = lane >> 3;
    float asrc = g_ad[(long)s * 128 + r * 4 + h];
    float adst = g_ad[(long)d * 128 + 32 + r * 4 + h];
    float er   = g_er[r * HEADS + h];
    float ex = __expf(lreluf(asrc + adst + er));
    if ((lane & 7) == 0) atomicAdd(g_den + (long)d * HEADS + h, ex);
    uint2 raw = *(const uint2*)(g_xr + ((long)r * Nn + s) * HID + lane * 4);
    float2 x01 = __half22float2(*(__half2*)&raw.x);
    float2 x23 = __half22float2(*(__half2*)&raw.y);
    float* o = g_msg + (long)d * HID + lane * 4;
    asm volatile("red.global.add.v4.f32 [%0], {%1,%2,%3,%4};"
                 :: "l"(o), "f"(x01.x * ex), "f"(x01.y * ex),
                    "f"(x23.x * ex), "f"(x23.y * ex)
                 : "memory");
}

// ---------------- post: normalize + root + elu + residual + LN2(fp16) ----------
__global__ void post_kernel(const float* __restrict__ x,
                            const float* __restrict__ w,
                            const float* __restrict__ b,
                            float* __restrict__ x1out, int Nn) {
    int gw = (blockIdx.x * blockDim.x + threadIdx.x) >> 5;
    int lane = threadIdx.x & 31;
    if (gw >= Nn) return;
    int h = lane >> 3;
    float den = g_den[(long)gw * HEADS + h];
    float inv = 1.0f / (den + 1e-16f);
    float4 mg = *(const float4*)(g_msg + (size_t)gw * HID + lane * 4);
    float4 rt = *(const float4*)(g_outc + (size_t)gw * HID + lane * 4);
    float4 oc;
    oc.x = eluf(mg.x * inv + rt.x);
    oc.y = eluf(mg.y * inv + rt.y);
    oc.z = eluf(mg.z * inv + rt.z);
    oc.w = eluf(mg.w * inv + rt.w);
    float4 xv = *(const float4*)(x + (size_t)gw * HID + lane * 4);
    float4 x1 = make_float4(xv.x + oc.x, xv.y + oc.y, xv.z + oc.z, xv.w + oc.w);
    *(float4*)(x1out + (size_t)gw * HID + lane * 4) = x1;
    float s = x1.x + x1.y + x1.z + x1.w;
    float q = x1.x * x1.x + x1.y * x1.y + x1.z * x1.z + x1.w * x1.w;
    #pragma unroll
    for (int o = 16; o; o >>= 1) {
        s += __shfl_xor_sync(0xffffffffu, s, o);
        q += __shfl_xor_sync(0xffffffffu, q, o);
    }
    float mu = s * (1.0f / HID);
    float var = q * (1.0f / HID) - mu * mu;
    float rstd = rsqrtf(var + 1e-5f);
    float4 wv = *(const float4*)(w + lane * 4);
    float4 bv = *(const float4*)(b + lane * 4);
    __half2 o01 = __floats2half2_rn((x1.x - mu) * rstd * wv.x + bv.x,
                                    (x1.y - mu) * rstd * wv.y + bv.y);
    __half2 o23 = __floats2half2_rn((x1.z - mu) * rstd * wv.z + bv.z,
                                    (x1.w - mu) * rstd * wv.w + bv.w);
    *(uint2*)(g_h2 + (size_t)gw * HID + lane * 4) =
        make_uint2(*(unsigned*)&o01, *(unsigned*)&o23);
}

// ---------------- launch ----------------
extern "C" void kernel_launch(void* const* d_in, const int* in_sizes, int n_in,
                              void* d_out, int out_size) {
    const float* x          = (const float*)d_in[0];
    const float* weight     = (const float*)d_in[1];
    const float* root_w     = (const float*)d_in[2];
    const float* edge_emb   = (const float*)d_in[3];
    const float* att_src    = (const float*)d_in[4];
    const float* att_dst    = (const float*)d_in[5];
    const float* att_edge   = (const float*)d_in[6];
    const float* bias       = (const float*)d_in[7];
    const float* n1w        = (const float*)d_in[8];
    const float* n1b        = (const float*)d_in[9];
    const float* n2w        = (const float*)d_in[10];
    const float* n2b        = (const float*)d_in[11];
    const float* ffn_w1     = (const float*)d_in[12];
    const float* ffn_b1     = (const float*)d_in[13];
    const float* ffn_w2     = (const float*)d_in[14];
    const float* ffn_b2     = (const float*)d_in[15];
    const int*   edge_index = (const int*)d_in[16];
    const int*   edge_type  = (const int*)d_in[17];
    float* out = (float*)d_out;

    int N = in_sizes[0] / HID;
    int E = in_sizes[17];
    int R = in_sizes[1] / (HID * HID);

    static int smem_set = 0;
    if (!smem_set) {
        cudaFuncSetAttribute(gemm_f16,
            cudaFuncAttributeMaxDynamicSharedMemorySize, SMEM_BYTES);
        smem_set = 1;
    }

    __half *p_h1, *p_xr, *p_h2, *p_t;
    float *p_ad, *p_wattp, *p_outc;
    cudaGetSymbolAddress((void**)&p_h1,    g_h1);
    cudaGetSymbolAddress((void**)&p_xr,    g_xr);
    cudaGetSymbolAddress((void**)&p_ad,    g_ad);
    cudaGetSymbolAddress((void**)&p_wattp, g_wattp);
    cudaGetSymbolAddress((void**)&p_outc,  g_outc);
    cudaGetSymbolAddress((void**)&p_h2,    g_h2);
    cudaGetSymbolAddress((void**)&p_t,     g_t);

    int rowBlocks = (N + 7) / 8;
    int mTiles    = (N + 127) / 128;

    init_kernel<<<(N * HID / 4 + 255) / 256, 256>>>(N);
    er_kernel<<<1, 32>>>(edge_emb, att_edge);
    watt_kernel<<<64, 256>>>(weight, att_src, att_dst);
    ln_kernel<<<rowBlocks, 256>>>(x, n1w, n1b, p_h1, N);

    // attention dots: g_ad = h1 @ w_att (fp32 out)
    gemm_f16<<<dim3(mTiles, 1, 1), 256, SMEM_BYTES>>>(
        p_h1, p_wattp, p_ad, nullptr, nullptr, N, HID, 128, 0, 0, 0, 0);
    // relation projections: g_xr[r] = h1 @ weight[r]  (fp16 out)
    gemm_f16<<<dim3(mTiles, 1, R), 256, SMEM_BYTES>>>(
        p_h1, weight, p_xr, nullptr, nullptr, N, HID, HID, 0, 1,
        (long)HID * HID, (long)N * HID);
    // root term (+bias)
    gemm_f16<<<dim3(mTiles, 1, 1), 256, SMEM_BYTES>>>(
        p_h1, root_w, p_outc, bias, nullptr, N, HID, HID, 0, 0, 0, 0);

    // fused edge pass
    edge_pass<<<(E + 7) / 8, 256>>>(edge_index, edge_type, E, N);

    post_kernel<<<rowBlocks, 256>>>(x, n2w, n2b, out, N);

    // FFN (t in fp16)
    gemm_f16<<<dim3(mTiles, 4, 1), 256, SMEM_BYTES>>>(
        p_h2, ffn_w1, p_t, ffn_b1, nullptr, N, HID, FFDIM, 1, 1, 0, 0);
    gemm_f16<<<dim3(mTiles, 1, 1), 256, SMEM_BYTES>>>(
        p_t, ffn_w2, out, ffn_b2, out, N, FFDIM, HID, 0, 0, 0, 0);
}

// round 8
// speedup vs baseline: 2.2751x; 1.2639x over previous
#include <cuda_runtime.h>
#include <cuda_fp16.h>
#include <math.h>

#define HID   128
#define MAXN  50000
#define MAXE  800000
#define RNUM  8
#define HEADS 4
#define FFDIM 512

// fp16 weight buffer offsets (halves)
#define OFF_XR   0
#define OFF_ROOT (RNUM*HID*HID)                 // 131072
#define OFF_WATT (OFF_ROOT + HID*HID)           // 147456
#define OFF_FFN1 (OFF_WATT + HID*HID)           // 163840
#define OFF_FFN2 (OFF_FFN1 + HID*FFDIM)         // 229376
#define WH_TOTAL (OFF_FFN2 + FFDIM*HID)         // 294912

// ---------------- scratch (device globals: allocation-free rule) ----------------
__device__ __half   g_h1  [(size_t)MAXN*HID];       // LN1(x), fp16
__device__ __half   g_xr  [(size_t)RNUM*MAXN*HID];  // relation projections, fp16
__device__ float    g_ad  [(size_t)MAXN*128];       // per-node attn dots
__device__ float    g_outc[(size_t)MAXN*HID];       // root GEMM + bias
__device__ __half   g_h2  [(size_t)MAXN*HID];       // LN2 out, fp16
__device__ __half   g_t   [(size_t)MAXN*FFDIM];     // FFN hidden, fp16
__device__ float    g_er  [32];                     // edge-emb dots (r*4+h)
__device__ __half   g_wh  [WH_TOTAL];               // all weights fp16
// CSR
__device__ int      g_deg [MAXN];
__device__ int      g_rowptr[MAXN + 1];
__device__ int      g_pos [MAXN];
__device__ int      g_bsum[256];
__device__ int      g_rec [MAXE];                   // src | (r<<16)

// ---------------- helpers ----------------
__device__ __forceinline__ float geluf(float v) {
    return 0.5f * v * (1.0f + erff(v * 0.7071067811865475f));
}
__device__ __forceinline__ float eluf(float v) {
    return v > 0.0f ? v : expm1f(v);
}
__device__ __forceinline__ float lreluf(float v) {
    return v > 0.0f ? v : 0.2f * v;
}

// ---------------- small prep kernels ----------------
__global__ void init_kernel(int Nn) {
    int i = blockIdx.x * blockDim.x + threadIdx.x;
    if (i < Nn) g_deg[i] = 0;
}

__global__ void er_kernel(const float* __restrict__ emb,
                          const float* __restrict__ att_edge) {
    int t = threadIdx.x;                 // 32 threads: index r*4+h
    int r = t >> 2, h = t & 3;
    float s = 0.0f;
    #pragma unroll
    for (int d = 0; d < 32; d++)
        s += emb[r * HID + h * 32 + d] * att_edge[h * 32 + d];
    g_er[t] = s;
}

__global__ void conv_kernel(const float* __restrict__ src,
                            __half* __restrict__ dst, int n4) {
    int i = blockIdx.x * blockDim.x + threadIdx.x;
    if (i >= n4) return;
    float4 v = ((const float4*)src)[i];
    __half2 a = __floats2half2_rn(v.x, v.y);
    __half2 b = __floats2half2_rn(v.z, v.w);
    ((uint2*)dst)[i] = make_uint2(*(unsigned*)&a, *(unsigned*)&b);
}

// w_att[i][c]: c<32: src dots col r*4+h; 32..63: dst; 64..127: zero (fp16 out)
__global__ void watt_kernel(const float* __restrict__ weight,
                            const float* __restrict__ att_src,
                            const float* __restrict__ att_dst) {
    int idx = blockIdx.x * blockDim.x + threadIdx.x;
    if (idx >= 128 * 128) return;
    int i = idx >> 7, c = idx & 127;
    float s = 0.0f;
    if (c < 64) {
        const float* vec = (c < 32) ? att_src : att_dst;
        int cc = c & 31;
        int r = cc >> 2, h = cc & 3;
        const float* wrow = weight + (long)r * HID * HID + (long)i * HID + h * 32;
        #pragma unroll
        for (int d = 0; d < 32; d++) s += wrow[d] * vec[h * 32 + d];
    }
    g_wh[OFF_WATT + i * 128 + c] = __float2half(s);
}

// ---------------- layernorm (warp per row) -> fp16 out ----------------
__global__ void ln_kernel(const float* __restrict__ x,
                          const float* __restrict__ w,
                          const float* __restrict__ b,
                          __half* __restrict__ out, int Nn) {
    int gw = (blockIdx.x * blockDim.x + threadIdx.x) >> 5;
    int lane = threadIdx.x & 31;
    if (gw >= Nn) return;
    const float4 v = *(const float4*)(x + (size_t)gw * HID + lane * 4);
    float s = v.x + v.y + v.z + v.w;
    float q = v.x * v.x + v.y * v.y + v.z * v.z + v.w * v.w;
    #pragma unroll
    for (int o = 16; o; o >>= 1) {
        s += __shfl_xor_sync(0xffffffffu, s, o);
        q += __shfl_xor_sync(0xffffffffu, q, o);
    }
    float mu = s * (1.0f / HID);
    float var = q * (1.0f / HID) - mu * mu;
    float rstd = rsqrtf(var + 1e-5f);
    float4 wv = *(const float4*)(w + lane * 4);
    float4 bv = *(const float4*)(b + lane * 4);
    __half2 o01 = __floats2half2_rn((v.x - mu) * rstd * wv.x + bv.x,
                                    (v.y - mu) * rstd * wv.y + bv.y);
    __half2 o23 = __floats2half2_rn((v.z - mu) * rstd * wv.z + bv.z,
                                    (v.w - mu) * rstd * wv.w + bv.w);
    *(uint2*)(out + (size_t)gw * HID + lane * 4) =
        make_uint2(*(unsigned*)&o01, *(unsigned*)&o23);
}

// ---------------- CSR build ----------------
__global__ void hist_kernel(const int* __restrict__ ei, int E) {
    int e = blockIdx.x * blockDim.x + threadIdx.x;
    if (e < E) atomicAdd(&g_deg[ei[E + e]], 1);
}
__global__ void scan1_kernel(int Nn) {
    __shared__ int sh[256];
    int i = blockIdx.x * 256 + threadIdx.x;
    int v = (i < Nn) ? g_deg[i] : 0;
    sh[threadIdx.x] = v;
    __syncthreads();
    #pragma unroll
    for (int o = 1; o < 256; o <<= 1) {
        int t = (threadIdx.x >= o) ? sh[threadIdx.x - o] : 0;
        __syncthreads();
        sh[threadIdx.x] += t;
        __syncthreads();
    }
    if (i < Nn) g_rowptr[i] = sh[threadIdx.x] - v;   // local exclusive
    if (threadIdx.x == 255) g_bsum[blockIdx.x] = sh[255];
}
__global__ void scan2_kernel(int nb) {
    __shared__ int sh[256];
    int t = threadIdx.x;
    int v = (t < nb) ? g_bsum[t] : 0;
    sh[t] = v;
    __syncthreads();
    #pragma unroll
    for (int o = 1; o < 256; o <<= 1) {
        int tv = (t >= o) ? sh[t - o] : 0;
        __syncthreads();
        sh[t] += tv;
        __syncthreads();
    }
    if (t < nb) g_bsum[t] = sh[t] - v;               // exclusive block offsets
}
__global__ void scan3_kernel(int Nn, int E) {
    int i = blockIdx.x * 256 + threadIdx.x;
    if (i < Nn) {
        int rp = g_rowptr[i] + g_bsum[i >> 8];
        g_rowptr[i] = rp;
        g_pos[i] = rp;
    }
    if (i == 0) g_rowptr[Nn] = E;
}
__global__ void scatter_kernel(const int* __restrict__ ei,
                               const int* __restrict__ et, int E) {
    int e = blockIdx.x * blockDim.x + threadIdx.x;
    if (e >= E) return;
    int d = ei[E + e];
    int p = atomicAdd(&g_pos[d], 1);
    g_rec[p] = ei[e] | (et[e] << 16);
}

// ---------------- fp16 tensor-core GEMM (cp.async A+B + ldmatrix + m16n8k16) ----
#define SROW 136
#define SMEM_BYTES (2 * 128 * SROW * 2)

__global__ __launch_bounds__(256, 2)
void gemm_f16(const __half* __restrict__ A, const __half* __restrict__ B,
              void* __restrict__ C, const float* __restrict__ bias,
              const float* __restrict__ resid,
              int M, int K, int ncols, int act, int outHalf,
              long strideB, long strideC) {
    extern __shared__ __half sm[];
    __half* As = sm;                 // [128][SROW]
    __half* Bs = sm + 128 * SROW;    // [128][SROW]

    const __half* Bb = B + (long)blockIdx.z * strideB;
    const int m0 = blockIdx.x * 128;
    const int n0 = blockIdx.y * 128;
    const int tid = threadIdx.x;
    const int lane = tid & 31, wid = tid >> 5;
    const int wm = wid >> 2, wn = wid & 3;
    const int g = lane >> 2, tg = lane & 3;

    float acc[4][4][4];
    #pragma unroll
    for (int i = 0; i < 4; i++)
        #pragma unroll
        for (int j = 0; j < 4; j++)
            #pragma unroll
            for (int c = 0; c < 4; c++) acc[i][j][c] = 0.0f;

    unsigned as_base = (unsigned)__cvta_generic_to_shared(As);
    unsigned bs_base = (unsigned)__cvta_generic_to_shared(Bs);
    const int a_row = (lane & 15);
    const int a_koff = (lane >> 4) << 3;
    const int b_krow = (lane & 15);

    for (int k0 = 0; k0 < K; k0 += 128) {
        if (k0) __syncthreads();
        // A: 128 rows x 16 x 16B, 8 copies/thread
        #pragma unroll
        for (int l = 0; l < 8; l++) {
            int idx = tid + l * 256;
            int row = idx >> 4, q = idx & 15;
            bool ok = (m0 + row < M);
            const __half* src = A + (ok ? ((long)(m0 + row) * K + k0 + q * 8) : 0);
            unsigned dst = as_base + ((unsigned)(row * SROW + q * 8) << 1);
            int sz = ok ? 16 : 0;
            asm volatile("cp.async.ca.shared.global [%0], [%1], 16, %2;"
                         :: "r"(dst), "l"(src), "r"(sz));
        }
        // B: 128 k-rows x 16 x 16B, 8 copies/thread (raw fp16)
        #pragma unroll
        for (int l = 0; l < 8; l++) {
            int idx = tid + l * 256;
            int row = idx >> 4, q = idx & 15;
            const __half* src = Bb + (long)(k0 + row) * ncols + n0 + q * 8;
            unsigned dst = bs_base + ((unsigned)(row * SROW + q * 8) << 1);
            asm volatile("cp.async.ca.shared.global [%0], [%1], 16;"
                         :: "r"(dst), "l"(src));
        }
        asm volatile("cp.async.commit_group;");
        asm volatile("cp.async.wait_group 0;");
        __syncthreads();

        #pragma unroll
        for (int kk = 0; kk < 8; kk++) {
            const int k16 = kk * 16;
            unsigned af[4][4], bf[4][2];
            #pragma unroll
            for (int tm = 0; tm < 4; tm++) {
                int rb = wm * 64 + tm * 16;
                unsigned addr = as_base +
                    (((rb + a_row) * SROW + k16 + a_koff) << 1);
                asm volatile(
                    "ldmatrix.sync.aligned.m8n8.x4.shared.b16 {%0,%1,%2,%3}, [%4];"
                    : "=r"(af[tm][0]), "=r"(af[tm][1]),
                      "=r"(af[tm][2]), "=r"(af[tm][3])
                    : "r"(addr));
            }
            #pragma unroll
            for (int tn = 0; tn < 4; tn++) {
                int cb = wn * 32 + tn * 8;
                unsigned addr = bs_base +
                    (((k16 + b_krow) * SROW + cb) << 1);
                asm volatile(
                    "ldmatrix.sync.aligned.m8n8.x2.trans.shared.b16 {%0,%1}, [%2];"
                    : "=r"(bf[tn][0]), "=r"(bf[tn][1])
                    : "r"(addr));
            }
            #pragma unroll
            for (int tm = 0; tm < 4; tm++)
                #pragma unroll
                for (int tn = 0; tn < 4; tn++) {
                    asm volatile(
                        "mma.sync.aligned.m16n8k16.row.col.f32.f16.f16.f32 "
                        "{%0,%1,%2,%3}, {%4,%5,%6,%7}, {%8,%9}, {%0,%1,%2,%3};"
                        : "+f"(acc[tm][tn][0]), "+f"(acc[tm][tn][1]),
                          "+f"(acc[tm][tn][2]), "+f"(acc[tm][tn][3])
                        : "r"(af[tm][0]), "r"(af[tm][1]),
                          "r"(af[tm][2]), "r"(af[tm][3]),
                          "r"(bf[tn][0]), "r"(bf[tn][1]));
                }
        }
    }

    #pragma unroll
    for (int tm = 0; tm < 4; tm++) {
        int r0 = m0 + wm * 64 + tm * 16 + g;
        #pragma unroll
        for (int tn = 0; tn < 4; tn++) {
            int col = n0 + wn * 32 + tn * 8 + 2 * tg;
            float2 bv = make_float2(0.f, 0.f);
            if (bias) bv = *(const float2*)(bias + col);
            #pragma unroll
            for (int half_ = 0; half_ < 2; half_++) {
                int row = r0 + half_ * 8;
                if (row >= M) continue;
                float v0 = acc[tm][tn][half_*2+0] + bv.x;
                float v1 = acc[tm][tn][half_*2+1] + bv.y;
                if (act == 1) { v0 = geluf(v0); v1 = geluf(v1); }
                if (resid) {
                    float2 rr = *(const float2*)(resid + (long)row * ncols + col);
                    v0 += rr.x; v1 += rr.y;
                }
                if (outHalf) {
                    __half* Ch = (__half*)C + blockIdx.z * strideC;
                    __half2 hv = __floats2half2_rn(v0, v1);
                    *(__half2*)(Ch + (long)row * ncols + col) = hv;
                } else {
                    float* Cf = (float*)C + blockIdx.z * strideC;
                    *(float2*)(Cf + (long)row * ncols + col) = make_float2(v0, v1);
                }
            }
        }
    }
}

// ------ fused aggregation: softmax-weighted gather + root + elu + resid + LN2 ---
// warp per destination node; register accumulation (no atomics).
__global__ void aggregate_kernel(const float* __restrict__ x,
                                 const float* __restrict__ w,
                                 const float* __restrict__ b,
                                 float* __restrict__ x1out, int Nn) {
    int gw = (blockIdx.x * blockDim.x + threadIdx.x) >> 5;
    int lane = threadIdx.x & 31;
    if (gw >= Nn) return;
    int h = lane >> 3;
    // dst-side dots (+er), one value per (r*4+h) in lane r*4+h
    float adv = g_ad[(long)gw * 128 + 32 + lane] + g_er[lane];
    int beg = g_rowptr[gw];
    int end = g_rowptr[gw + 1];
    float den = 0.0f;
    float a0 = 0.f, a1 = 0.f, a2 = 0.f, a3 = 0.f;
    for (int e = beg; e < end; e++) {
        int rec = g_rec[e];
        int s = rec & 0xFFFF;
        int r = rec >> 16;
        float logit = __shfl_sync(0xffffffffu, adv, r * 4 + h)
                    + g_ad[(long)s * 128 + r * 4 + h];
        float ex = __expf(lreluf(logit));
        den += ex;
        uint2 raw = *(const uint2*)(g_xr + ((long)r * Nn + s) * HID + lane * 4);
        float2 x01 = __half22float2(*(__half2*)&raw.x);
        float2 x23 = __half22float2(*(__half2*)&raw.y);
        a0 += x01.x * ex; a1 += x01.y * ex;
        a2 += x23.x * ex; a3 += x23.y * ex;
    }
    float inv = 1.0f / (den + 1e-16f);
    float4 rt = *(const float4*)(g_outc + (size_t)gw * HID + lane * 4);
    float4 oc;
    oc.x = eluf(a0 * inv + rt.x);
    oc.y = eluf(a1 * inv + rt.y);
    oc.z = eluf(a2 * inv + rt.z);
    oc.w = eluf(a3 * inv + rt.w);
    float4 xv = *(const float4*)(x + (size_t)gw * HID + lane * 4);
    float4 x1 = make_float4(xv.x + oc.x, xv.y + oc.y, xv.z + oc.z, xv.w + oc.w);
    *(float4*)(x1out + (size_t)gw * HID + lane * 4) = x1;
    // LN2
    float s = x1.x + x1.y + x1.z + x1.w;
    float q = x1.x * x1.x + x1.y * x1.y + x1.z * x1.z + x1.w * x1.w;
    #pragma unroll
    for (int o = 16; o; o >>= 1) {
        s += __shfl_xor_sync(0xffffffffu, s, o);
        q += __shfl_xor_sync(0xffffffffu, q, o);
    }
    float mu = s * (1.0f / HID);
    float var = q * (1.0f / HID) - mu * mu;
    float rstd = rsqrtf(var + 1e-5f);
    float4 wv = *(const float4*)(w + lane * 4);
    float4 bv = *(const float4*)(b + lane * 4);
    __half2 o01 = __floats2half2_rn((x1.x - mu) * rstd * wv.x + bv.x,
                                    (x1.y - mu) * rstd * wv.y + bv.y);
    __half2 o23 = __floats2half2_rn((x1.z - mu) * rstd * wv.z + bv.z,
                                    (x1.w - mu) * rstd * wv.w + bv.w);
    *(uint2*)(g_h2 + (size_t)gw * HID + lane * 4) =
        make_uint2(*(unsigned*)&o01, *(unsigned*)&o23);
}

// ---------------- launch ----------------
extern "C" void kernel_launch(void* const* d_in, const int* in_sizes, int n_in,
                              void* d_out, int out_size) {
    const float* x          = (const float*)d_in[0];
    const float* weight     = (const float*)d_in[1];
    const float* root_w     = (const float*)d_in[2];
    const float* edge_emb   = (const float*)d_in[3];
    const float* att_src    = (const float*)d_in[4];
    const float* att_dst    = (const float*)d_in[5];
    const float* att_edge   = (const float*)d_in[6];
    const float* bias       = (const float*)d_in[7];
    const float* n1w        = (const float*)d_in[8];
    const float* n1b        = (const float*)d_in[9];
    const float* n2w        = (const float*)d_in[10];
    const float* n2b        = (const float*)d_in[11];
    const float* ffn_w1     = (const float*)d_in[12];
    const float* ffn_b1     = (const float*)d_in[13];
    const float* ffn_w2     = (const float*)d_in[14];
    const float* ffn_b2     = (const float*)d_in[15];
    const int*   edge_index = (const int*)d_in[16];
    const int*   edge_type  = (const int*)d_in[17];
    float* out = (float*)d_out;

    int N = in_sizes[0] / HID;
    int E = in_sizes[17];
    int R = in_sizes[1] / (HID * HID);

    static int smem_set = 0;
    if (!smem_set) {
        cudaFuncSetAttribute(gemm_f16,
            cudaFuncAttributeMaxDynamicSharedMemorySize, SMEM_BYTES);
        smem_set = 1;
    }

    __half *p_h1, *p_xr, *p_h2, *p_t, *p_wh;
    float *p_ad, *p_outc;
    cudaGetSymbolAddress((void**)&p_h1,   g_h1);
    cudaGetSymbolAddress((void**)&p_xr,   g_xr);
    cudaGetSymbolAddress((void**)&p_ad,   g_ad);
    cudaGetSymbolAddress((void**)&p_outc, g_outc);
    cudaGetSymbolAddress((void**)&p_h2,   g_h2);
    cudaGetSymbolAddress((void**)&p_t,    g_t);
    cudaGetSymbolAddress((void**)&p_wh,   g_wh);

    int rowBlocks = (N + 7) / 8;
    int mTiles    = (N + 127) / 128;
    int nScanB    = (N + 255) / 256;

    // prep
    init_kernel<<<(N + 255) / 256, 256>>>(N);
    er_kernel<<<1, 32>>>(edge_emb, att_edge);
    conv_kernel<<<(R * HID * HID / 4 + 255) / 256, 256>>>(weight, p_wh + OFF_XR,
                                                          R * HID * HID / 4);
    conv_kernel<<<(HID * HID / 4 + 255) / 256, 256>>>(root_w, p_wh + OFF_ROOT,
                                                      HID * HID / 4);
    conv_kernel<<<(HID * FFDIM / 4 + 255) / 256, 256>>>(ffn_w1, p_wh + OFF_FFN1,
                                                        HID * FFDIM / 4);
    conv_kernel<<<(FFDIM * HID / 4 + 255) / 256, 256>>>(ffn_w2, p_wh + OFF_FFN2,
                                                        FFDIM * HID / 4);
    watt_kernel<<<64, 256>>>(weight, att_src, att_dst);
    ln_kernel<<<rowBlocks, 256>>>(x, n1w, n1b, p_h1, N);

    // CSR build
    hist_kernel<<<(E + 255) / 256, 256>>>(edge_index, E);
    scan1_kernel<<<nScanB, 256>>>(N);
    scan2_kernel<<<1, 256>>>(nScanB);
    scan3_kernel<<<nScanB, 256>>>(N, E);
    scatter_kernel<<<(E + 255) / 256, 256>>>(edge_index, edge_type, E);

    // GEMMs
    gemm_f16<<<dim3(mTiles, 1, 1), 256, SMEM_BYTES>>>(
        p_h1, p_wh + OFF_WATT, p_ad, nullptr, nullptr, N, HID, 128, 0, 0, 0, 0);
    gemm_f16<<<dim3(mTiles, 1, R), 256, SMEM_BYTES>>>(
        p_h1, p_wh + OFF_XR, p_xr, nullptr, nullptr, N, HID, HID, 0, 1,
        (long)HID * HID, (long)N * HID);
    gemm_f16<<<dim3(mTiles, 1, 1), 256, SMEM_BYTES>>>(
        p_h1, p_wh + OFF_ROOT, p_outc, bias, nullptr, N, HID, HID, 0, 0, 0, 0);

    // fused aggregation + post (out = x1, g_h2 = LN2)
    aggregate_kernel<<<rowBlocks, 256>>>(x, n2w, n2b, out, N);

    // FFN
    gemm_f16<<<dim3(mTiles, 4, 1), 256, SMEM_BYTES>>>(
        p_h2, p_wh + OFF_FFN1, p_t, ffn_b1, nullptr, N, HID, FFDIM, 1, 1, 0, 0);
    gemm_f16<<<dim3(mTiles, 1, 1), 256, SMEM_BYTES>>>(
        p_t, p_wh + OFF_FFN2, out, ffn_b2, out, N, FFDIM, HID, 0, 0, 0, 0);
}

// round 9
// speedup vs baseline: 2.3884x; 1.0498x over previous
#include <cuda_runtime.h>
#include <cuda_fp16.h>
#include <math.h>

#define HID   128
#define MAXN  50000
#define MAXE  800000
#define RNUM  8
#define HEADS 4
#define FFDIM 512

// fp16 weight buffer offsets (halves)
#define OFF_XR   0
#define OFF_ROOT (RNUM*HID*HID)                 // 131072
#define OFF_WATT (OFF_ROOT + HID*HID)           // 147456
#define OFF_FFN1 (OFF_WATT + HID*HID)           // 163840
#define OFF_FFN2 (OFF_FFN1 + HID*FFDIM)         // 229376
#define WH_TOTAL (OFF_FFN2 + FFDIM*HID)         // 294912

// ---------------- scratch ----------------
__device__ __half   g_h1  [(size_t)MAXN*HID];
__device__ __half   g_xr  [(size_t)RNUM*MAXN*HID];
__device__ float    g_ad  [(size_t)MAXN*128];
__device__ float    g_outc[(size_t)MAXN*HID];
__device__ __half   g_h2  [(size_t)MAXN*HID];
__device__ __half   g_t   [(size_t)MAXN*FFDIM];
__device__ float    g_er  [32];
__device__ __half   g_wh  [WH_TOTAL];
// CSR
__device__ int      g_deg [MAXN];
__device__ int      g_rowptr[MAXN + 1];
__device__ int      g_pos [MAXN];
__device__ int      g_bsum[256];
__device__ int      g_rec [MAXE];

// ---------------- helpers ----------------
__device__ __forceinline__ float geluf(float v) {
    return 0.5f * v * (1.0f + erff(v * 0.7071067811865475f));
}
__device__ __forceinline__ float eluf(float v) {
    return v > 0.0f ? v : expm1f(v);
}
__device__ __forceinline__ float lreluf(float v) {
    return v > 0.0f ? v : 0.2f * v;
}

// ---------------- one fused prep kernel ----------------
// ranges: [0,32768) conv weight | [.., +4096) root | +16384 ffn1 | +16384 ffn2
//         +16384 watt | +32 er | +N deg-zero
#define P_W0 0
#define P_W1 (P_W0 + RNUM*HID*HID/4)      // 32768
#define P_W2 (P_W1 + HID*HID/4)           // 36864
#define P_W3 (P_W2 + HID*FFDIM/4)         // 53248
#define P_W4 (P_W3 + FFDIM*HID/4)         // 69632
#define P_ER (P_W4 + 128*128)             // 86016
#define P_DEG (P_ER + 32)                 // 86048
__global__ void prep_kernel(const float* __restrict__ weight,
                            const float* __restrict__ root_w,
                            const float* __restrict__ ffn_w1,
                            const float* __restrict__ ffn_w2,
                            const float* __restrict__ att_src,
                            const float* __restrict__ att_dst,
                            const float* __restrict__ att_edge,
                            const float* __restrict__ emb,
                            int Nn) {
    int i = blockIdx.x * blockDim.x + threadIdx.x;
    if (i < P_W4) {
        const float* src; __half* dst; int off;
        if (i < P_W1)      { src = weight; dst = g_wh + OFF_XR;   off = i - P_W0; }
        else if (i < P_W2) { src = root_w; dst = g_wh + OFF_ROOT; off = i - P_W1; }
        else if (i < P_W3) { src = ffn_w1; dst = g_wh + OFF_FFN1; off = i - P_W2; }
        else               { src = ffn_w2; dst = g_wh + OFF_FFN2; off = i - P_W3; }
        float4 v = ((const float4*)src)[off];
        __half2 a = __floats2half2_rn(v.x, v.y);
        __half2 b = __floats2half2_rn(v.z, v.w);
        ((uint2*)dst)[off] = make_uint2(*(unsigned*)&a, *(unsigned*)&b);
    } else if (i < P_ER) {
        int idx = i - P_W4;
        int row = idx >> 7, c = idx & 127;
        float s = 0.0f;
        if (c < 64) {
            const float* vec = (c < 32) ? att_src : att_dst;
            int cc = c & 31;
            int r = cc >> 2, h = cc & 3;
            const float* wrow = weight + (long)r * HID * HID + (long)row * HID + h * 32;
            #pragma unroll
            for (int d = 0; d < 32; d++) s += wrow[d] * vec[h * 32 + d];
        }
        g_wh[OFF_WATT + row * 128 + c] = __float2half(s);
    } else if (i < P_DEG) {
        int t = i - P_ER;                // r*4+h
        int r = t >> 2, h = t & 3;
        float s = 0.0f;
        #pragma unroll
        for (int d = 0; d < 32; d++)
            s += emb[r * HID + h * 32 + d] * att_edge[h * 32 + d];
        g_er[t] = s;
    } else if (i < P_DEG + Nn) {
        g_deg[i - P_DEG] = 0;
    }
}

// ---------------- layernorm (warp per row) -> fp16 out ----------------
__global__ void ln_kernel(const float* __restrict__ x,
                          const float* __restrict__ w,
                          const float* __restrict__ b,
                          __half* __restrict__ out, int Nn) {
    int gw = (blockIdx.x * blockDim.x + threadIdx.x) >> 5;
    int lane = threadIdx.x & 31;
    if (gw >= Nn) return;
    const float4 v = *(const float4*)(x + (size_t)gw * HID + lane * 4);
    float s = v.x + v.y + v.z + v.w;
    float q = v.x * v.x + v.y * v.y + v.z * v.z + v.w * v.w;
    #pragma unroll
    for (int o = 16; o; o >>= 1) {
        s += __shfl_xor_sync(0xffffffffu, s, o);
        q += __shfl_xor_sync(0xffffffffu, q, o);
    }
    float mu = s * (1.0f / HID);
    float var = q * (1.0f / HID) - mu * mu;
    float rstd = rsqrtf(var + 1e-5f);
    float4 wv = *(const float4*)(w + lane * 4);
    float4 bv = *(const float4*)(b + lane * 4);
    __half2 o01 = __floats2half2_rn((v.x - mu) * rstd * wv.x + bv.x,
                                    (v.y - mu) * rstd * wv.y + bv.y);
    __half2 o23 = __floats2half2_rn((v.z - mu) * rstd * wv.z + bv.z,
                                    (v.w - mu) * rstd * wv.w + bv.w);
    *(uint2*)(out + (size_t)gw * HID + lane * 4) =
        make_uint2(*(unsigned*)&o01, *(unsigned*)&o23);
}

// ---------------- CSR build ----------------
__global__ void hist_kernel(const int* __restrict__ ei, int E) {
    int e = blockIdx.x * blockDim.x + threadIdx.x;
    if (e < E) atomicAdd(&g_deg[ei[E + e]], 1);
}
__global__ void scan1_kernel(int Nn) {
    __shared__ int sh[256];
    int i = blockIdx.x * 256 + threadIdx.x;
    int v = (i < Nn) ? g_deg[i] : 0;
    sh[threadIdx.x] = v;
    __syncthreads();
    #pragma unroll
    for (int o = 1; o < 256; o <<= 1) {
        int t = (threadIdx.x >= o) ? sh[threadIdx.x - o] : 0;
        __syncthreads();
        sh[threadIdx.x] += t;
        __syncthreads();
    }
    if (i < Nn) g_rowptr[i] = sh[threadIdx.x] - v;
    if (threadIdx.x == 255) g_bsum[blockIdx.x] = sh[255];
}
__global__ void scan2_kernel(int nb) {
    __shared__ int sh[256];
    int t = threadIdx.x;
    int v = (t < nb) ? g_bsum[t] : 0;
    sh[t] = v;
    __syncthreads();
    #pragma unroll
    for (int o = 1; o < 256; o <<= 1) {
        int tv = (t >= o) ? sh[t - o] : 0;
        __syncthreads();
        sh[t] += tv;
        __syncthreads();
    }
    if (t < nb) g_bsum[t] = sh[t] - v;
}
__global__ void scan3_kernel(int Nn, int E) {
    int i = blockIdx.x * 256 + threadIdx.x;
    if (i < Nn) {
        int rp = g_rowptr[i] + g_bsum[i >> 8];
        g_rowptr[i] = rp;
        g_pos[i] = rp;
    }
    if (i == 0) g_rowptr[Nn] = E;
}
__global__ void scatter_kernel(const int* __restrict__ ei,
                               const int* __restrict__ et, int E) {
    int e = blockIdx.x * blockDim.x + threadIdx.x;
    if (e >= E) return;
    int d = ei[E + e];
    int p = atomicAdd(&g_pos[d], 1);
    g_rec[p] = ei[e] | (et[e] << 16);
}

// -------- batched front GEMM: z=0 watt->ad(f32); z=1..8 xr(f16); z=9 root ------
// M x 128 x 128, A = g_h1, single K chunk.
#define SROW 136
#define SMEM_BYTES (2 * 128 * SROW * 2)

__global__ __launch_bounds__(256, 2)
void gemm_front(const __half* __restrict__ A, const float* __restrict__ bias,
                int M, int Nn) {
    extern __shared__ __half sm[];
    __half* As = sm;
    __half* Bs = sm + 128 * SROW;

    const int z = blockIdx.z;
    const __half* Bb;
    int outHalf;
    if (z == 0)      { Bb = g_wh + OFF_WATT; outHalf = 0; }
    else if (z <= 8) { Bb = g_wh + OFF_XR + (long)(z - 1) * HID * HID; outHalf = 1; }
    else             { Bb = g_wh + OFF_ROOT; outHalf = 0; }

    const int m0 = blockIdx.x * 128;
    const int tid = threadIdx.x;
    const int lane = tid & 31, wid = tid >> 5;
    const int wm = wid >> 2, wn = wid & 3;
    const int g = lane >> 2, tg = lane & 3;

    float acc[4][4][4];
    #pragma unroll
    for (int i = 0; i < 4; i++)
        #pragma unroll
        for (int j = 0; j < 4; j++)
            #pragma unroll
            for (int c = 0; c < 4; c++) acc[i][j][c] = 0.0f;

    unsigned as_base = (unsigned)__cvta_generic_to_shared(As);
    unsigned bs_base = (unsigned)__cvta_generic_to_shared(Bs);
    const int a_row = (lane & 15);
    const int a_koff = (lane >> 4) << 3;
    const int b_krow = (lane & 15);

    #pragma unroll
    for (int l = 0; l < 8; l++) {
        int idx = tid + l * 256;
        int row = idx >> 4, q = idx & 15;
        bool ok = (m0 + row < M);
        const __half* src = A + (ok ? ((long)(m0 + row) * HID + q * 8) : 0);
        unsigned dst = as_base + ((unsigned)(row * SROW + q * 8) << 1);
        int sz = ok ? 16 : 0;
        asm volatile("cp.async.ca.shared.global [%0], [%1], 16, %2;"
                     :: "r"(dst), "l"(src), "r"(sz));
    }
    #pragma unroll
    for (int l = 0; l < 8; l++) {
        int idx = tid + l * 256;
        int row = idx >> 4, q = idx & 15;
        const __half* src = Bb + (long)row * HID + q * 8;
        unsigned dst = bs_base + ((unsigned)(row * SROW + q * 8) << 1);
        asm volatile("cp.async.ca.shared.global [%0], [%1], 16;"
                     :: "r"(dst), "l"(src));
    }
    asm volatile("cp.async.commit_group;");
    asm volatile("cp.async.wait_group 0;");
    __syncthreads();

    #pragma unroll
    for (int kk = 0; kk < 8; kk++) {
        const int k16 = kk * 16;
        unsigned af[4][4], bf[4][2];
        #pragma unroll
        for (int tm = 0; tm < 4; tm++) {
            int rb = wm * 64 + tm * 16;
            unsigned addr = as_base + (((rb + a_row) * SROW + k16 + a_koff) << 1);
            asm volatile(
                "ldmatrix.sync.aligned.m8n8.x4.shared.b16 {%0,%1,%2,%3}, [%4];"
                : "=r"(af[tm][0]), "=r"(af[tm][1]),
                  "=r"(af[tm][2]), "=r"(af[tm][3])
                : "r"(addr));
        }
        #pragma unroll
        for (int tn = 0; tn < 4; tn++) {
            int cb = wn * 32 + tn * 8;
            unsigned addr = bs_base + (((k16 + b_krow) * SROW + cb) << 1);
            asm volatile(
                "ldmatrix.sync.aligned.m8n8.x2.trans.shared.b16 {%0,%1}, [%2];"
                : "=r"(bf[tn][0]), "=r"(bf[tn][1])
                : "r"(addr));
        }
        #pragma unroll
        for (int tm = 0; tm < 4; tm++)
            #pragma unroll
            for (int tn = 0; tn < 4; tn++) {
                asm volatile(
                    "mma.sync.aligned.m16n8k16.row.col.f32.f16.f16.f32 "
                    "{%0,%1,%2,%3}, {%4,%5,%6,%7}, {%8,%9}, {%0,%1,%2,%3};"
                    : "+f"(acc[tm][tn][0]), "+f"(acc[tm][tn][1]),
                      "+f"(acc[tm][tn][2]), "+f"(acc[tm][tn][3])
                    : "r"(af[tm][0]), "r"(af[tm][1]),
                      "r"(af[tm][2]), "r"(af[tm][3]),
                      "r"(bf[tn][0]), "r"(bf[tn][1]));
            }
    }

    #pragma unroll
    for (int tm = 0; tm < 4; tm++) {
        int r0 = m0 + wm * 64 + tm * 16 + g;
        #pragma unroll
        for (int tn = 0; tn < 4; tn++) {
            int col = wn * 32 + tn * 8 + 2 * tg;
            float2 bv = make_float2(0.f, 0.f);
            if (z == 9) bv = *(const float2*)(bias + col);
            #pragma unroll
            for (int half_ = 0; half_ < 2; half_++) {
                int row = r0 + half_ * 8;
                if (row >= M) continue;
                float v0 = acc[tm][tn][half_*2+0] + bv.x;
                float v1 = acc[tm][tn][half_*2+1] + bv.y;
                if (outHalf) {
                    __half* Ch = g_xr + (long)(z - 1) * Nn * HID;
                    __half2 hv = __floats2half2_rn(v0, v1);
                    *(__half2*)(Ch + (long)row * HID + col) = hv;
                } else {
                    float* Cf = (z == 0) ? g_ad : g_outc;
                    *(float2*)(Cf + (long)row * HID + col) = make_float2(v0, v1);
                }
            }
        }
    }
}

// ---------------- generic fp16 GEMM for FFN ----------------
__global__ __launch_bounds__(256, 2)
void gemm_f16(const __half* __restrict__ A, const __half* __restrict__ B,
              void* __restrict__ C, const float* __restrict__ bias,
              const float* __restrict__ resid,
              int M, int K, int ncols, int act, int outHalf) {
    extern __shared__ __half sm[];
    __half* As = sm;
    __half* Bs = sm + 128 * SROW;

    const int m0 = blockIdx.x * 128;
    const int n0 = blockIdx.y * 128;
    const int tid = threadIdx.x;
    const int lane = tid & 31, wid = tid >> 5;
    const int wm = wid >> 2, wn = wid & 3;
    const int g = lane >> 2, tg = lane & 3;

    float acc[4][4][4];
    #pragma unroll
    for (int i = 0; i < 4; i++)
        #pragma unroll
        for (int j = 0; j < 4; j++)
            #pragma unroll
            for (int c = 0; c < 4; c++) acc[i][j][c] = 0.0f;

    unsigned as_base = (unsigned)__cvta_generic_to_shared(As);
    unsigned bs_base = (unsigned)__cvta_generic_to_shared(Bs);
    const int a_row = (lane & 15);
    const int a_koff = (lane >> 4) << 3;
    const int b_krow = (lane & 15);

    for (int k0 = 0; k0 < K; k0 += 128) {
        if (k0) __syncthreads();
        #pragma unroll
        for (int l = 0; l < 8; l++) {
            int idx = tid + l * 256;
            int row = idx >> 4, q = idx & 15;
            bool ok = (m0 + row < M);
            const __half* src = A + (ok ? ((long)(m0 + row) * K + k0 + q * 8) : 0);
            unsigned dst = as_base + ((unsigned)(row * SROW + q * 8) << 1);
            int sz = ok ? 16 : 0;
            asm volatile("cp.async.ca.shared.global [%0], [%1], 16, %2;"
                         :: "r"(dst), "l"(src), "r"(sz));
        }
        #pragma unroll
        for (int l = 0; l < 8; l++) {
            int idx = tid + l * 256;
            int row = idx >> 4, q = idx & 15;
            const __half* src = B + (long)(k0 + row) * ncols + n0 + q * 8;
            unsigned dst = bs_base + ((unsigned)(row * SROW + q * 8) << 1);
            asm volatile("cp.async.ca.shared.global [%0], [%1], 16;"
                         :: "r"(dst), "l"(src));
        }
        asm volatile("cp.async.commit_group;");
        asm volatile("cp.async.wait_group 0;");
        __syncthreads();

        #pragma unroll
        for (int kk = 0; kk < 8; kk++) {
            const int k16 = kk * 16;
            unsigned af[4][4], bf[4][2];
            #pragma unroll
            for (int tm = 0; tm < 4; tm++) {
                int rb = wm * 64 + tm * 16;
                unsigned addr = as_base + (((rb + a_row) * SROW + k16 + a_koff) << 1);
                asm volatile(
                    "ldmatrix.sync.aligned.m8n8.x4.shared.b16 {%0,%1,%2,%3}, [%4];"
                    : "=r"(af[tm][0]), "=r"(af[tm][1]),
                      "=r"(af[tm][2]), "=r"(af[tm][3])
                    : "r"(addr));
            }
            #pragma unroll
            for (int tn = 0; tn < 4; tn++) {
                int cb = wn * 32 + tn * 8;
                unsigned addr = bs_base + (((k16 + b_krow) * SROW + cb) << 1);
                asm volatile(
                    "ldmatrix.sync.aligned.m8n8.x2.trans.shared.b16 {%0,%1}, [%2];"
                    : "=r"(bf[tn][0]), "=r"(bf[tn][1])
                    : "r"(addr));
            }
            #pragma unroll
            for (int tm = 0; tm < 4; tm++)
                #pragma unroll
                for (int tn = 0; tn < 4; tn++) {
                    asm volatile(
                        "mma.sync.aligned.m16n8k16.row.col.f32.f16.f16.f32 "
                        "{%0,%1,%2,%3}, {%4,%5,%6,%7}, {%8,%9}, {%0,%1,%2,%3};"
                        : "+f"(acc[tm][tn][0]), "+f"(acc[tm][tn][1]),
                          "+f"(acc[tm][tn][2]), "+f"(acc[tm][tn][3])
                        : "r"(af[tm][0]), "r"(af[tm][1]),
                          "r"(af[tm][2]), "r"(af[tm][3]),
                          "r"(bf[tn][0]), "r"(bf[tn][1]));
                }
        }
    }

    #pragma unroll
    for (int tm = 0; tm < 4; tm++) {
        int r0 = m0 + wm * 64 + tm * 16 + g;
        #pragma unroll
        for (int tn = 0; tn < 4; tn++) {
            int col = n0 + wn * 32 + tn * 8 + 2 * tg;
            float2 bv = make_float2(0.f, 0.f);
            if (bias) bv = *(const float2*)(bias + col);
            #pragma unroll
            for (int half_ = 0; half_ < 2; half_++) {
                int row = r0 + half_ * 8;
                if (row >= M) continue;
                float v0 = acc[tm][tn][half_*2+0] + bv.x;
                float v1 = acc[tm][tn][half_*2+1] + bv.y;
                if (act == 1) { v0 = geluf(v0); v1 = geluf(v1); }
                if (resid) {
                    float2 rr = *(const float2*)(resid + (long)row * ncols + col);
                    v0 += rr.x; v1 += rr.y;
                }
                if (outHalf) {
                    __half2 hv = __floats2half2_rn(v0, v1);
                    *(__half2*)((__half*)C + (long)row * ncols + col) = hv;
                } else {
                    *(float2*)((float*)C + (long)row * ncols + col) = make_float2(v0, v1);
                }
            }
        }
    }
}

// ------ fused aggregation (2x unrolled) + root + elu + resid + LN2 ------
__global__ void aggregate_kernel(const float* __restrict__ x,
                                 const float* __restrict__ w,
                                 const float* __restrict__ b,
                                 float* __restrict__ x1out, int Nn) {
    int gw = (blockIdx.x * blockDim.x + threadIdx.x) >> 5;
    int lane = threadIdx.x & 31;
    if (gw >= Nn) return;
    int h = lane >> 3;
    float adv = g_ad[(long)gw * 128 + 32 + lane] + g_er[lane];
    int beg = g_rowptr[gw];
    int end = g_rowptr[gw + 1];
    float den = 0.0f;
    float a0 = 0.f, a1 = 0.f, a2 = 0.f, a3 = 0.f;
    int e = beg;
    for (; e + 2 <= end; e += 2) {
        int rec0 = __ldg(&g_rec[e]);
        int rec1 = __ldg(&g_rec[e + 1]);
        int s0 = rec0 & 0xFFFF, r0 = rec0 >> 16;
        int s1 = rec1 & 0xFFFF, r1 = rec1 >> 16;
        float ads0 = __ldg(&g_ad[(long)s0 * 128 + r0 * 4 + h]);
        float ads1 = __ldg(&g_ad[(long)s1 * 128 + r1 * 4 + h]);
        uint2 raw0 = *(const uint2*)(g_xr + ((long)r0 * Nn + s0) * HID + lane * 4);
        uint2 raw1 = *(const uint2*)(g_xr + ((long)r1 * Nn + s1) * HID + lane * 4);
        float l0 = __shfl_sync(0xffffffffu, adv, r0 * 4 + h) + ads0;
        float l1 = __shfl_sync(0xffffffffu, adv, r1 * 4 + h) + ads1;
        float ex0 = __expf(lreluf(l0));
        float ex1 = __expf(lreluf(l1));
        den += ex0 + ex1;
        float2 p01 = __half22float2(*(__half2*)&raw0.x);
        float2 p23 = __half22float2(*(__half2*)&raw0.y);
        a0 += p01.x * ex0; a1 += p01.y * ex0;
        a2 += p23.x * ex0; a3 += p23.y * ex0;
        float2 q01 = __half22float2(*(__half2*)&raw1.x);
        float2 q23 = __half22float2(*(__half2*)&raw1.y);
        a0 += q01.x * ex1; a1 += q01.y * ex1;
        a2 += q23.x * ex1; a3 += q23.y * ex1;
    }
    if (e < end) {
        int rec = __ldg(&g_rec[e]);
        int s = rec & 0xFFFF, r = rec >> 16;
        float logit = __shfl_sync(0xffffffffu, adv, r * 4 + h)
                    + __ldg(&g_ad[(long)s * 128 + r * 4 + h]);
        float ex = __expf(lreluf(logit));
        den += ex;
        uint2 raw = *(const uint2*)(g_xr + ((long)r * Nn + s) * HID + lane * 4);
        float2 p01 = __half22float2(*(__half2*)&raw.x);
        float2 p23 = __half22float2(*(__half2*)&raw.y);
        a0 += p01.x * ex; a1 += p01.y * ex;
        a2 += p23.x * ex; a3 += p23.y * ex;
    }
    float inv = 1.0f / (den + 1e-16f);
    float4 rt = *(const float4*)(g_outc + (size_t)gw * HID + lane * 4);
    float4 oc;
    oc.x = eluf(a0 * inv + rt.x);
    oc.y = eluf(a1 * inv + rt.y);
    oc.z = eluf(a2 * inv + rt.z);
    oc.w = eluf(a3 * inv + rt.w);
    float4 xv = *(const float4*)(x + (size_t)gw * HID + lane * 4);
    float4 x1 = make_float4(xv.x + oc.x, xv.y + oc.y, xv.z + oc.z, xv.w + oc.w);
    *(float4*)(x1out + (size_t)gw * HID + lane * 4) = x1;
    float s = x1.x + x1.y + x1.z + x1.w;
    float q = x1.x * x1.x + x1.y * x1.y + x1.z * x1.z + x1.w * x1.w;
    #pragma unroll
    for (int o = 16; o; o >>= 1) {
        s += __shfl_xor_sync(0xffffffffu, s, o);
        q += __shfl_xor_sync(0xffffffffu, q, o);
    }
    float mu = s * (1.0f / HID);
    float var = q * (1.0f / HID) - mu * mu;
    float rstd = rsqrtf(var + 1e-5f);
    float4 wv = *(const float4*)(w + lane * 4);
    float4 bv = *(const float4*)(b + lane * 4);
    __half2 o01 = __floats2half2_rn((x1.x - mu) * rstd * wv.x + bv.x,
                                    (x1.y - mu) * rstd * wv.y + bv.y);
    __half2 o23 = __floats2half2_rn((x1.z - mu) * rstd * wv.z + bv.z,
                                    (x1.w - mu) * rstd * wv.w + bv.w);
    *(uint2*)(g_h2 + (size_t)gw * HID + lane * 4) =
        make_uint2(*(unsigned*)&o01, *(unsigned*)&o23);
}

// ---------------- launch ----------------
extern "C" void kernel_launch(void* const* d_in, const int* in_sizes, int n_in,
                              void* d_out, int out_size) {
    const float* x          = (const float*)d_in[0];
    const float* weight     = (const float*)d_in[1];
    const float* root_w     = (const float*)d_in[2];
    const float* edge_emb   = (const float*)d_in[3];
    const float* att_src    = (const float*)d_in[4];
    const float* att_dst    = (const float*)d_in[5];
    const float* att_edge   = (const float*)d_in[6];
    const float* bias       = (const float*)d_in[7];
    const float* n1w        = (const float*)d_in[8];
    const float* n1b        = (const float*)d_in[9];
    const float* n2w        = (const float*)d_in[10];
    const float* n2b        = (const float*)d_in[11];
    const float* ffn_w1     = (const float*)d_in[12];
    const float* ffn_b1     = (const float*)d_in[13];
    const float* ffn_w2     = (const float*)d_in[14];
    const float* ffn_b2     = (const float*)d_in[15];
    const int*   edge_index = (const int*)d_in[16];
    const int*   edge_type  = (const int*)d_in[17];
    float* out = (float*)d_out;

    int N = in_sizes[0] / HID;
    int E = in_sizes[17];

    static int smem_set = 0;
    if (!smem_set) {
        cudaFuncSetAttribute(gemm_front,
            cudaFuncAttributeMaxDynamicSharedMemorySize, SMEM_BYTES);
        cudaFuncSetAttribute(gemm_f16,
            cudaFuncAttributeMaxDynamicSharedMemorySize, SMEM_BYTES);
        smem_set = 1;
    }

    __half *p_h1, *p_h2, *p_t, *p_wh;
    cudaGetSymbolAddress((void**)&p_h1, g_h1);
    cudaGetSymbolAddress((void**)&p_h2, g_h2);
    cudaGetSymbolAddress((void**)&p_t,  g_t);
    cudaGetSymbolAddress((void**)&p_wh, g_wh);

    int rowBlocks = (N + 7) / 8;
    int mTiles    = (N + 127) / 128;
    int nScanB    = (N + 255) / 256;
    int prepBlocks = (P_DEG + N + 255) / 256;

    prep_kernel<<<prepBlocks, 256>>>(weight, root_w, ffn_w1, ffn_w2,
                                     att_src, att_dst, att_edge, edge_emb, N);
    ln_kernel<<<rowBlocks, 256>>>(x, n1w, n1b, p_h1, N);

    hist_kernel<<<(E + 255) / 256, 256>>>(edge_index, E);
    scan1_kernel<<<nScanB, 256>>>(N);
    scan2_kernel<<<1, 256>>>(nScanB);
    scan3_kernel<<<nScanB, 256>>>(N, E);
    scatter_kernel<<<(E + 255) / 256, 256>>>(edge_index, edge_type, E);

    gemm_front<<<dim3(mTiles, 1, 10), 256, SMEM_BYTES>>>(p_h1, bias, N, N);

    aggregate_kernel<<<rowBlocks, 256>>>(x, n2w, n2b, out, N);

    gemm_f16<<<dim3(mTiles, 4, 1), 256, SMEM_BYTES>>>(
        p_h2, p_wh + OFF_FFN1, p_t, ffn_b1, nullptr, N, HID, FFDIM, 1, 1);
    gemm_f16<<<dim3(mTiles, 1, 1), 256, SMEM_BYTES>>>(
        p_t, p_wh + OFF_FFN2, out, ffn_b2, out, N, FFDIM, HID, 0, 0);
}